// round 9
// baseline (speedup 1.0000x reference)
#include <cuda_runtime.h>
#include <cuda_fp16.h>
#include <cstdint>

// ---------------- problem constants (fixed shapes) ----------------
#define NMAX   100000
#define FDIM   128
#define HDIM   128
#define EDIM   64
#define RREL   3
#define TMAXC  2048      // max unique targets (2*B)
#define S1MAX  49152     // max |S1| (expected ~30K)
#define E2MAX  131072    // max layer-2 edges (expected ~33K)

// ---------------- device scratch (static, no allocation) ----------------
__device__ int   g_tid[NMAX];       // node -> target compact id (-1 none)
__device__ int   g_s1id[NMAX];      // node -> S1 compact id (-1 none)
__device__ int   g_tnodes[TMAXC];
__device__ int   g_t2s1[TMAXC];     // target idx -> s1 idx
__device__ int   g_s1nodes[S1MAX];
__device__ int   g_tcount;
__device__ int   g_s1count;
__device__ int   g_e2count;
__device__ int   g_e2src[E2MAX];
__device__ int   g_e2bin[E2MAX];
__device__ float g_agg1[(size_t)RREL * S1MAX * FDIM];   // ~75.5 MB
__device__ int   g_cnt1[RREL * S1MAX];
__device__ float g_h1[(size_t)S1MAX * HDIM];            // ~25 MB
__device__ float g_agg2[RREL * TMAXC * HDIM];
__device__ int   g_cnt2[RREL * TMAXC];
__device__ float g_node[TMAXC * EDIM];
// transposed fp16 layer-1 weights: [N=128][K=512]
__device__ __align__(16) unsigned short g_Wt1[HDIM * 512];

__device__ __forceinline__ void red_add_v4(float* p, float4 v) {
    asm volatile("red.global.add.v4.f32 [%0], {%1,%2,%3,%4};"
                 :: "l"(p), "f"(v.x), "f"(v.y), "f"(v.z), "f"(v.w) : "memory");
}

__device__ __forceinline__ uint32_t smem_u32(const void* p) {
    uint32_t a;
    asm("{ .reg .u64 t; cvta.to.shared.u64 t, %1; cvt.u32.u64 %0, t; }"
        : "=r"(a) : "l"(p));
    return a;
}
__device__ __forceinline__ uint32_t sw128(uint32_t off) {
    return off ^ ((off >> 3) & 0x70);
}
__device__ __forceinline__ void ldsm4(uint32_t r[4], uint32_t addr) {
    asm volatile("ldmatrix.sync.aligned.m8n8.x4.shared.b16 {%0,%1,%2,%3}, [%4];"
                 : "=r"(r[0]), "=r"(r[1]), "=r"(r[2]), "=r"(r[3]) : "r"(addr));
}
__device__ __forceinline__ void mma16816(float* c, const uint32_t* a, const uint32_t* b) {
    asm volatile(
        "mma.sync.aligned.m16n8k16.row.col.f32.f16.f16.f32 "
        "{%0,%1,%2,%3}, {%4,%5,%6,%7}, {%8,%9}, {%0,%1,%2,%3};"
        : "+f"(c[0]), "+f"(c[1]), "+f"(c[2]), "+f"(c[3])
        : "r"(a[0]), "r"(a[1]), "r"(a[2]), "r"(a[3]), "r"(b[0]), "r"(b[1]));
}
__device__ __forceinline__ void cp_async16(uint32_t smem_dst, const void* gsrc) {
    asm volatile("cp.async.ca.shared.global [%0], [%1], 16;"
                 :: "r"(smem_dst), "l"(gsrc) : "memory");
}
#define CP_COMMIT() asm volatile("cp.async.commit_group;" ::: "memory")
#define CP_WAIT0()  asm volatile("cp.async.wait_group 0;" ::: "memory")

// ---------------- k0: init maps/counters + fp16 weight transpose ----------------
__global__ void k0_init(int N, const float* __restrict__ Wrel,
                        const float* __restrict__ Wroot) {
    int i = blockIdx.x * blockDim.x + threadIdx.x;
    int stride = gridDim.x * blockDim.x;
    for (int j = i; j < N; j += stride) { g_tid[j] = -1; g_s1id[j] = -1; }
    for (int j = i; j < RREL * S1MAX; j += stride) g_cnt1[j] = 0;
    for (int j = i; j < RREL * TMAXC; j += stride) g_cnt2[j] = 0;
    for (int j = i; j < RREL * TMAXC * HDIM; j += stride) g_agg2[j] = 0.f;
    for (int j = i; j < HDIM * 512; j += stride) {
        int n = j >> 9;
        int k = j & 511;
        float v = (k < 384) ? Wrel[(size_t)k * HDIM + n]
                            : Wroot[(size_t)(k - 384) * HDIM + n];
        g_Wt1[j] = __half_as_ushort(__float2half_rn(v));
    }
    if (i == 0) { g_tcount = 0; g_s1count = 0; g_e2count = 0; }
}

// ---------------- k1: mark target set T = nest ∪ food ----------------
__global__ void k1_targets(const int* __restrict__ nest,
                           const int* __restrict__ food, int B) {
    int i = blockIdx.x * blockDim.x + threadIdx.x;
    if (i >= 2 * B) return;
    int v = (i < B) ? nest[i] : food[i - B];
    if (atomicCAS(&g_tid[v], -1, -2) == -1) {
        int id = atomicAdd(&g_tcount, 1);       // <= 2*B <= TMAXC
        g_tnodes[id] = v;
        int sid = atomicAdd(&g_s1count, 1);
        g_s1nodes[sid] = v;
        g_s1id[v] = sid;
        g_t2s1[id] = sid;
        g_tid[v] = id;
    }
}

// ---------------- k2: scan edges (ILP=4), keep dst∈T, build S1 ----------------
__global__ void k2_scan(const int* __restrict__ esrc, const int* __restrict__ edst,
                        const int* __restrict__ etyp, int E) {
    int lane = threadIdx.x & 31;
    int warpId = (blockIdx.x * blockDim.x + threadIdx.x) >> 5;
    int nwarp = (gridDim.x * blockDim.x) >> 5;
    for (int c0 = warpId * 128; c0 < E; c0 += nwarp * 128) {
        int d[4], td[4];
#pragma unroll
        for (int j = 0; j < 4; j++) {
            int e = c0 + j * 32 + lane;
            d[j] = (e < E) ? edst[e] : -1;
        }
#pragma unroll
        for (int j = 0; j < 4; j++)
            td[j] = (d[j] >= 0) ? g_tid[d[j]] : -1;
#pragma unroll
        for (int j = 0; j < 4; j++) {
            bool pass = td[j] >= 0;
            unsigned mask = __ballot_sync(0xffffffffu, pass);
            if (mask == 0) continue;
            if (pass) {
                int e = c0 + j * 32 + lane;
                int t = etyp[e];
                int s = esrc[e];
                int leader = __ffs(mask) - 1;
                int rank = __popc(mask & ((1u << lane) - 1));
                int base = 0;
                if (lane == leader) base = atomicAdd(&g_e2count, __popc(mask));
                base = __shfl_sync(mask, base, leader);
                int idx = base + rank;
                int bin = t * TMAXC + td[j];
                atomicAdd(&g_cnt2[bin], 1);
                if (idx < E2MAX) { g_e2src[idx] = s; g_e2bin[idx] = bin; }
                if (atomicCAS(&g_s1id[s], -1, -2) == -1) {
                    int id = atomicAdd(&g_s1count, 1);
                    if (id < S1MAX) { g_s1nodes[id] = s; g_s1id[s] = id; }
                }
            }
        }
    }
}

// ---------------- k3: zero exactly the used part of agg1 ----------------
__global__ void k3_zero() {
    int cnt = g_s1count; if (cnt > S1MAX) cnt = S1MAX;
    int per4 = cnt * (FDIM / 4);                // float4 count per relation
    int r = blockIdx.y;
    float4* base = (float4*)&g_agg1[(size_t)r * S1MAX * FDIM];
    float4 z = make_float4(0.f, 0.f, 0.f, 0.f);
    for (int j = blockIdx.x * blockDim.x + threadIdx.x; j < per4;
         j += gridDim.x * blockDim.x)
        base[j] = z;
}

// ---------------- k4: layer-1 aggregation (ILP=4 filter + warp RED) ----------
__global__ void k4_agg1(const int* __restrict__ esrc, const int* __restrict__ edst,
                        const int* __restrict__ etyp, const float* __restrict__ x,
                        int E) {
    int lane = threadIdx.x & 31;
    int warpId = (blockIdx.x * blockDim.x + threadIdx.x) >> 5;
    int nwarp = (gridDim.x * blockDim.x) >> 5;
    for (int c0 = warpId * 128; c0 < E; c0 += nwarp * 128) {
        int d[4], s[4], t[4], sid[4];
#pragma unroll
        for (int j = 0; j < 4; j++) {
            int e = c0 + j * 32 + lane;
            bool v = e < E;
            d[j] = v ? edst[e] : -1;
            s[j] = v ? esrc[e] : 0;
            t[j] = v ? etyp[e] : 0;
        }
#pragma unroll
        for (int j = 0; j < 4; j++)
            sid[j] = (d[j] >= 0) ? g_s1id[d[j]] : -1;
#pragma unroll
        for (int j = 0; j < 4; j++) {
            bool pass = sid[j] >= 0;
            unsigned mask = __ballot_sync(0xffffffffu, pass);
            int bin = t[j] * S1MAX + sid[j];
            int ss = s[j];
            while (mask) {
                int src_lane = __ffs(mask) - 1;
                mask &= mask - 1;
                int sb = __shfl_sync(0xffffffffu, ss, src_lane);
                int bb = __shfl_sync(0xffffffffu, bin, src_lane);
                if (lane == 0) atomicAdd(&g_cnt1[bb], 1);
                float4 v = *(const float4*)&x[(size_t)sb * FDIM + lane * 4];
                red_add_v4(&g_agg1[(size_t)bb * FDIM + lane * 4], v);
            }
        }
    }
}

// ---------------- k5: mma.sync fp16-split GEMM1 (2 passes) ----------------
// h1 = relu([agg1/c | x] @ [Wrel1;Wroot1] + b1)
// Per CTA: BM=128, N=128, K=512 in 8 groups of 64. Double-buffered (2 x 48KB).
#define SM5_BUF 49152
#define SM5_AHI 0
#define SM5_ALO 16384
#define SM5_B   32768
#define SM5_TOTAL (2 * SM5_BUF)

__global__ __launch_bounds__(256) void k5_mma(const float* __restrict__ x,
                                              const float* __restrict__ bias) {
    extern __shared__ char smem[];
    int M = g_s1count; if (M > S1MAX) M = S1MAX;
    int row0 = blockIdx.x * 128;
    if (row0 >= M) return;
    uint32_t sb = smem_u32(smem);
    int tid = threadIdx.x;
    int wid = tid >> 5;
    int lane = tid & 31;
    int wm = wid >> 1;          // 0..3  (warp m tile: 32 rows)
    int wn = wid & 1;           // 0..1  (warp n tile: 64 cols)

    int row  = tid >> 1;        // 0..127 (loader row)
    int half = tid & 1;         // cols half*32..+32 of the 64-chunk
    int gi = row0 + row;
    bool valid = gi < M;
    int gR = valid ? gi : 0;
    int anode = valid ? g_s1nodes[gR] : 0;

    float4 va[8];
    // ---- group A load into regs ----
    auto loadA = [&](int g) {
        const float* src;
        float inv = 1.0f;
        if (g < 6) {
            int seg = g >> 1;
            src = &g_agg1[((size_t)(seg * S1MAX + gR)) * FDIM + (g & 1) * 64 + half * 32];
            int c = g_cnt1[seg * S1MAX + gR];
            inv = 1.0f / (float)(c > 1 ? c : 1);
        } else {
            src = &x[(size_t)anode * FDIM + (g - 6) * 64 + half * 32];
        }
#pragma unroll
        for (int j = 0; j < 8; j++) {
            float4 v = make_float4(0.f, 0.f, 0.f, 0.f);
            if (valid) {
                v = *(const float4*)&src[j * 4];
                if (g < 6) { v.x *= inv; v.y *= inv; v.z *= inv; v.w *= inv; }
            }
            va[j] = v;
        }
    };
    // ---- convert + STS A hi/lo (fp16) ----
    auto stsA = [&](int buf) {
#pragma unroll
        for (int j = 0; j < 8; j++) {
            float4 v = va[j];
            __half2 h01 = __floats2half2_rn(v.x, v.y);
            __half2 h23 = __floats2half2_rn(v.z, v.w);
            float2 f01 = __half22float2(h01);
            float2 f23 = __half22float2(h23);
            __half2 l01 = __floats2half2_rn(v.x - f01.x, v.y - f01.y);
            __half2 l23 = __floats2half2_rn(v.z - f23.x, v.w - f23.y);
            uint32_t off = sw128(row * 128 + (half * 32 + j * 4) * 2);
            uint2 ph, pl;
            ph.x = *(uint32_t*)&h01; ph.y = *(uint32_t*)&h23;
            pl.x = *(uint32_t*)&l01; pl.y = *(uint32_t*)&l23;
            *(uint2*)(smem + buf * SM5_BUF + SM5_AHI + off) = ph;
            *(uint2*)(smem + buf * SM5_BUF + SM5_ALO + off) = pl;
        }
    };
    // ---- cp.async B tile (single fp16) ----
    auto cpB = [&](int g, int buf) {
        uint32_t base = sb + buf * SM5_BUF;
        const unsigned short* sW = &g_Wt1[row * 512 + g * 64 + half * 32];
#pragma unroll
        for (int j = 0; j < 4; j++) {
            uint32_t off = sw128(row * 128 + (half * 32 + j * 8) * 2);
            cp_async16(base + SM5_B + off, sW + j * 8);
        }
        CP_COMMIT();
    };

    float acc[2][8][4];
#pragma unroll
    for (int mt = 0; mt < 2; mt++)
#pragma unroll
        for (int n8 = 0; n8 < 8; n8++)
#pragma unroll
            for (int q = 0; q < 4; q++) acc[mt][n8][q] = 0.f;

    // prologue: group 0
    cpB(0, 0);
    loadA(0);
    stsA(0);
    CP_WAIT0();
    __syncthreads();

    for (int g = 0; g < 8; g++) {
        int cur = g & 1, nxt = cur ^ 1;
        if (g < 7) { cpB(g + 1, nxt); loadA(g + 1); }
        uint32_t bufb = sb + cur * SM5_BUF;
#pragma unroll
        for (int pass = 0; pass < 2; pass++) {
            uint32_t ab = bufb + ((pass == 1) ? SM5_ALO : SM5_AHI);
            uint32_t bb = bufb + SM5_B;
#pragma unroll
            for (int ks = 0; ks < 4; ks++) {
                uint32_t af[2][4];
#pragma unroll
                for (int mt = 0; mt < 2; mt++) {
                    int r = wm * 32 + mt * 16 + (lane & 7) + ((lane >> 3) & 1) * 8;
                    int cB = ks * 32 + (lane >> 4) * 16;
                    ldsm4(af[mt], ab + sw128(r * 128 + cB));
                }
                uint32_t bf[4][4];
#pragma unroll
                for (int nt = 0; nt < 4; nt++) {
                    int rn = wn * 64 + nt * 16 + (lane & 7) + (lane >> 4) * 8;
                    int cB = ks * 32 + ((lane >> 3) & 1) * 16;
                    ldsm4(bf[nt], bb + sw128(rn * 128 + cB));
                }
#pragma unroll
                for (int mt = 0; mt < 2; mt++)
#pragma unroll
                    for (int n8 = 0; n8 < 8; n8++)
                        mma16816(acc[mt][n8], af[mt], &bf[n8 >> 1][(n8 & 1) * 2]);
            }
        }
        if (g < 7) {
            stsA(nxt);
            CP_WAIT0();
            __syncthreads();
        }
    }

    // ---- epilogue: +bias, relu, store ----
#pragma unroll
    for (int mt = 0; mt < 2; mt++) {
#pragma unroll
        for (int n8 = 0; n8 < 8; n8++) {
            int r = row0 + wm * 32 + mt * 16 + (lane >> 2);
            int col = wn * 64 + n8 * 8 + (lane & 3) * 2;
            float2 bv = *(const float2*)&bias[col];
            if (r < M) {
                float2 o;
                o.x = fmaxf(acc[mt][n8][0] + bv.x, 0.f);
                o.y = fmaxf(acc[mt][n8][1] + bv.y, 0.f);
                *(float2*)&g_h1[(size_t)r * HDIM + col] = o;
            }
            if (r + 8 < M) {
                float2 o;
                o.x = fmaxf(acc[mt][n8][2] + bv.x, 0.f);
                o.y = fmaxf(acc[mt][n8][3] + bv.y, 0.f);
                *(float2*)&g_h1[(size_t)(r + 8) * HDIM + col] = o;
            }
        }
    }
}

// ---------------- k6: layer-2 edge aggregation (compacted edges) ------------
__global__ void k6_agg2() {
    int n2 = g_e2count; if (n2 > E2MAX) n2 = E2MAX;
    int w = (blockIdx.x * blockDim.x + threadIdx.x) >> 5;
    int lane = threadIdx.x & 31;
    int nw = (gridDim.x * blockDim.x) >> 5;
    for (int i = w; i < n2; i += nw) {
        int s = g_e2src[i];
        int bin = g_e2bin[i];
        int sid = g_s1id[s];
        if (sid < 0) continue;  // safety
        float4 v = *(const float4*)&g_h1[(size_t)sid * HDIM + lane * 4];
        red_add_v4(&g_agg2[(size_t)bin * HDIM + lane * 4], v);
    }
}

// ---------------- k7: GEMM2: node = [agg2/c | h1_T] @ [Wrel2;Wroot2] + b2 ----
__global__ __launch_bounds__(256) void k7_gemm_node(
    const float* __restrict__ Wrel, const float* __restrict__ Wroot,
    const float* __restrict__ bias) {
    int M = g_tcount; if (M > TMAXC) M = TMAXC;
    int row0 = blockIdx.x * 64;
    if (row0 >= M) return;
    __shared__ __align__(16) float As[16][64];
    __shared__ __align__(16) float Bs[16][64];
    int tid = threadIdx.x;
    int rg = tid >> 4;
    int cg = tid & 15;
    float acc[4][4];
#pragma unroll
    for (int m = 0; m < 4; m++)
#pragma unroll
        for (int n = 0; n < 4; n++) acc[m][n] = 0.f;

    int a_i = tid >> 2;
    int a_kk = (tid & 3) * 4;
    int gi = row0 + a_i;
    int hsrc = (gi < M) ? g_t2s1[gi] : 0;

    for (int kt = 0; kt < 32; kt++) {
        int k0 = kt * 16;
        float4 av = make_float4(0.f, 0.f, 0.f, 0.f);
        if (gi < M) {
            int k = k0 + a_kk;
            int seg = k >> 7;
            if (seg < 3) {
                av = *(const float4*)&g_agg2[((size_t)(seg * TMAXC + gi)) * HDIM + (k & 127)];
                int c = g_cnt2[seg * TMAXC + gi];
                float inv = 1.0f / (float)(c > 1 ? c : 1);
                av.x *= inv; av.y *= inv; av.z *= inv; av.w *= inv;
            } else {
                av = *(const float4*)&g_h1[(size_t)hsrc * HDIM + (k - 384)];
            }
        }
        As[a_kk + 0][a_i] = av.x;
        As[a_kk + 1][a_i] = av.y;
        As[a_kk + 2][a_i] = av.z;
        As[a_kk + 3][a_i] = av.w;
        {
            int kk = tid >> 4, col = (tid & 15) * 4;
            int k = k0 + kk;
            const float* srcp = (k < 384) ? &Wrel[(size_t)k * EDIM + col]
                                          : &Wroot[(size_t)(k - 384) * EDIM + col];
            *(float4*)&Bs[kk][col] = *(const float4*)srcp;
        }
        __syncthreads();
#pragma unroll
        for (int kk = 0; kk < 16; kk++) {
            float4 ta = *(float4*)&As[kk][rg * 4];
            float a4[4] = {ta.x, ta.y, ta.z, ta.w};
            float4 bb = *(float4*)&Bs[kk][cg * 4];
            float b4[4] = {bb.x, bb.y, bb.z, bb.w};
#pragma unroll
            for (int m = 0; m < 4; m++)
#pragma unroll
                for (int n = 0; n < 4; n++) acc[m][n] += a4[m] * b4[n];
        }
        __syncthreads();
    }
    float4 bv = *(const float4*)&bias[cg * 4];
#pragma unroll
    for (int m = 0; m < 4; m++) {
        int row = row0 + rg * 4 + m;
        if (row < M) {
            float4 o;
            o.x = acc[m][0] + bv.x;
            o.y = acc[m][1] + bv.y;
            o.z = acc[m][2] + bv.z;
            o.w = acc[m][3] + bv.w;
            *(float4*)&g_node[(size_t)row * EDIM + cg * 4] = o;
        }
    }
}

// ---------------- k8: out = tanh([node[nest]|node[food]] @ fc_W + fc_b) ------
__global__ void k8_final(const int* __restrict__ nest, const int* __restrict__ food,
                         const float* __restrict__ fcW, const float* __restrict__ fcb,
                         float* __restrict__ out) {
    __shared__ float pr[128];
    int b = blockIdx.x;
    int h = threadIdx.x;    // 0..127
    if (h < 64) {
        int tn = g_tid[nest[b]];
        pr[h] = g_node[tn * EDIM + h];
    } else {
        int tf = g_tid[food[b]];
        pr[h] = g_node[tf * EDIM + (h - 64)];
    }
    __syncthreads();
    float acc = fcb[h];
#pragma unroll 8
    for (int k = 0; k < 128; k++) acc = fmaf(pr[k], fcW[k * HDIM + h], acc);
    out[(size_t)b * HDIM + h] = tanhf(acc);
}

// ---------------- launch ----------------
extern "C" void kernel_launch(void* const* d_in, const int* in_sizes, int n_in,
                              void* d_out, int out_size) {
    const float* x      = (const float*)d_in[0];
    const int*   esrc   = (const int*)d_in[1];
    const int*   edst   = (const int*)d_in[2];
    const int*   etyp   = (const int*)d_in[3];
    // d_in[4] = edge_attr (unused by the reference output)
    const int*   nest   = (const int*)d_in[5];
    const int*   food   = (const int*)d_in[6];
    const float* Wrel1  = (const float*)d_in[7];
    const float* Wroot1 = (const float*)d_in[8];
    const float* b1     = (const float*)d_in[9];
    const float* Wrel2  = (const float*)d_in[10];
    const float* Wroot2 = (const float*)d_in[11];
    const float* b2     = (const float*)d_in[12];
    const float* fcW    = (const float*)d_in[13];
    const float* fcb    = (const float*)d_in[14];
    float* out = (float*)d_out;

    int N = in_sizes[0] / FDIM;
    int E = in_sizes[1];
    int B = in_sizes[5];

    cudaFuncSetAttribute(k5_mma, cudaFuncAttributeMaxDynamicSharedMemorySize, SM5_TOTAL);

    k0_init<<<1024, 256>>>(N, Wrel1, Wroot1);
    k1_targets<<<(2 * B + 255) / 256, 256>>>(nest, food, B);
    k2_scan<<<(E + 1023) / 1024, 256>>>(esrc, edst, etyp, E);
    {
        dim3 g(2048, 3, 1);
        k3_zero<<<g, 256>>>();
    }
    k4_agg1<<<4736, 256>>>(esrc, edst, etyp, x, E);
    k5_mma<<<S1MAX / 128, 256, SM5_TOTAL>>>(x, b1);
    k6_agg2<<<2048, 256>>>();
    k7_gemm_node<<<TMAXC / 64, 256>>>(Wrel2, Wroot2, b2);
    k8_final<<<B, 128>>>(nest, food, fcW, fcb, out);
}

// round 10
// speedup vs baseline: 1.0512x; 1.0512x over previous
#include <cuda_runtime.h>
#include <cuda_fp16.h>
#include <cstdint>

// ---------------- problem constants (fixed shapes) ----------------
#define NMAX   100000
#define FDIM   128
#define HDIM   128
#define EDIM   64
#define RREL   3
#define TMAXC  2048      // max unique targets (2*B)
#define S1MAX  49152     // max |S1| (expected ~30K)
#define E2MAX  131072    // max layer-2 edges (expected ~33K)

#define ZERO_BLOCKS 2048

// ---------------- device scratch (static, no allocation) ----------------
__device__ int   g_tid[NMAX];       // node -> target compact id (-1 none)
__device__ int   g_s1id[NMAX];      // node -> S1 compact id (-1 none)
__device__ int   g_tnodes[TMAXC];
__device__ int   g_t2s1[TMAXC];     // target idx -> s1 idx
__device__ int   g_s1nodes[S1MAX];
__device__ int   g_tcount;
__device__ int   g_s1count;
__device__ int   g_e2count;
__device__ int   g_e2src[E2MAX];
__device__ int   g_e2bin[E2MAX];
__device__ float g_agg1[(size_t)RREL * S1MAX * FDIM];   // ~75.5 MB
__device__ int   g_cnt1[RREL * S1MAX];
__device__ float g_h1[(size_t)S1MAX * HDIM];            // ~25 MB
__device__ float g_agg2[RREL * TMAXC * HDIM];
__device__ int   g_cnt2[RREL * TMAXC];
__device__ float g_node[TMAXC * EDIM];
// transposed fp16 layer-1 weights: [N=128][K=512]
__device__ __align__(16) unsigned short g_Wt1[HDIM * 512];

__device__ __forceinline__ void red_add_v4(float* p, float4 v) {
    asm volatile("red.global.add.v4.f32 [%0], {%1,%2,%3,%4};"
                 :: "l"(p), "f"(v.x), "f"(v.y), "f"(v.z), "f"(v.w) : "memory");
}

__device__ __forceinline__ uint32_t smem_u32(const void* p) {
    uint32_t a;
    asm("{ .reg .u64 t; cvta.to.shared.u64 t, %1; cvt.u32.u64 %0, t; }"
        : "=r"(a) : "l"(p));
    return a;
}
__device__ __forceinline__ uint32_t sw128(uint32_t off) {
    return off ^ ((off >> 3) & 0x70);
}
__device__ __forceinline__ void ldsm4(uint32_t r[4], uint32_t addr) {
    asm volatile("ldmatrix.sync.aligned.m8n8.x4.shared.b16 {%0,%1,%2,%3}, [%4];"
                 : "=r"(r[0]), "=r"(r[1]), "=r"(r[2]), "=r"(r[3]) : "r"(addr));
}
__device__ __forceinline__ void mma16816(float* c, const uint32_t* a, const uint32_t* b) {
    asm volatile(
        "mma.sync.aligned.m16n8k16.row.col.f32.f16.f16.f32 "
        "{%0,%1,%2,%3}, {%4,%5,%6,%7}, {%8,%9}, {%0,%1,%2,%3};"
        : "+f"(c[0]), "+f"(c[1]), "+f"(c[2]), "+f"(c[3])
        : "r"(a[0]), "r"(a[1]), "r"(a[2]), "r"(a[3]), "r"(b[0]), "r"(b[1]));
}
__device__ __forceinline__ void cp_async16(uint32_t smem_dst, const void* gsrc) {
    asm volatile("cp.async.ca.shared.global [%0], [%1], 16;"
                 :: "r"(smem_dst), "l"(gsrc) : "memory");
}
#define CP_COMMIT() asm volatile("cp.async.commit_group;" ::: "memory")
#define CP_WAIT0()  asm volatile("cp.async.wait_group 0;" ::: "memory")

// ---------------- k0: init maps/counters + fp16 weight transpose ----------------
__global__ void k0_init(int N, const float* __restrict__ Wrel,
                        const float* __restrict__ Wroot) {
    int i = blockIdx.x * blockDim.x + threadIdx.x;
    int stride = gridDim.x * blockDim.x;
    for (int j = i; j < N; j += stride) { g_tid[j] = -1; g_s1id[j] = -1; }
    for (int j = i; j < RREL * S1MAX; j += stride) g_cnt1[j] = 0;
    for (int j = i; j < RREL * TMAXC; j += stride) g_cnt2[j] = 0;
    for (int j = i; j < RREL * TMAXC * HDIM; j += stride) g_agg2[j] = 0.f;
    for (int j = i; j < HDIM * 512; j += stride) {
        int n = j >> 9;
        int k = j & 511;
        float v = (k < 384) ? Wrel[(size_t)k * HDIM + n]
                            : Wroot[(size_t)(k - 384) * HDIM + n];
        g_Wt1[j] = __half_as_ushort(__float2half_rn(v));
    }
    if (i == 0) { g_tcount = 0; g_s1count = 0; g_e2count = 0; }
}

// ---------------- k1: mark target set T = nest ∪ food ----------------
__global__ void k1_targets(const int* __restrict__ nest,
                           const int* __restrict__ food, int B) {
    int i = blockIdx.x * blockDim.x + threadIdx.x;
    if (i >= 2 * B) return;
    int v = (i < B) ? nest[i] : food[i - B];
    if (atomicCAS(&g_tid[v], -1, -2) == -1) {
        int id = atomicAdd(&g_tcount, 1);       // <= 2*B <= TMAXC
        g_tnodes[id] = v;
        int sid = atomicAdd(&g_s1count, 1);
        g_s1nodes[sid] = v;
        g_s1id[v] = sid;
        g_t2s1[id] = sid;
        g_tid[v] = id;
    }
}

// ---------------- k2: fused edge scan (dst∈T, build S1) + agg1 zeroing --------
// Blocks [0, scanBlocks): round-8 thread-per-edge scan.
// Blocks [scanBlocks, scanBlocks+ZERO_BLOCKS): zero the FULL agg1 region
// (no dependence on s1count) — overlaps store-bound zeroing with the
// latency-bound scan.
__global__ void k2_scan(const int* __restrict__ esrc, const int* __restrict__ edst,
                        const int* __restrict__ etyp, int E, int scanBlocks) {
    if ((int)blockIdx.x >= scanBlocks) {
        // ---- zero role ----
        const size_t per4 = (size_t)RREL * S1MAX * (FDIM / 4);
        float4* base = (float4*)g_agg1;
        float4 z = make_float4(0.f, 0.f, 0.f, 0.f);
        size_t start = (size_t)(blockIdx.x - scanBlocks) * blockDim.x + threadIdx.x;
        size_t stride = (size_t)ZERO_BLOCKS * blockDim.x;
        for (size_t j = start; j < per4; j += stride) base[j] = z;
        return;
    }
    // ---- scan role (identical to round-8 k2) ----
    int e = blockIdx.x * blockDim.x + threadIdx.x;
    bool pass = false;
    int td = -1;
    if (e < E) {
        td = g_tid[edst[e]];
        pass = (td >= 0);
    }
    unsigned mask = __ballot_sync(0xffffffffu, pass);
    if (!pass) return;
    int t = etyp[e];
    int s = esrc[e];
    int lane = threadIdx.x & 31;
    int leader = __ffs(mask) - 1;
    int rank = __popc(mask & ((1u << lane) - 1));
    int base = 0;
    if (lane == leader) base = atomicAdd(&g_e2count, __popc(mask));
    base = __shfl_sync(mask, base, leader);
    int idx = base + rank;
    int bin = t * TMAXC + td;
    atomicAdd(&g_cnt2[bin], 1);
    if (idx < E2MAX) { g_e2src[idx] = s; g_e2bin[idx] = bin; }
    if (atomicCAS(&g_s1id[s], -1, -2) == -1) {
        int id = atomicAdd(&g_s1count, 1);
        if (id < S1MAX) { g_s1nodes[id] = s; g_s1id[s] = id; }
    }
}

// ---------------- k4: layer-1 aggregation, single pass (round-8 form) --------
__global__ void k4_agg1(const int* __restrict__ esrc, const int* __restrict__ edst,
                        const int* __restrict__ etyp, const float* __restrict__ x,
                        int E) {
    int lane = threadIdx.x & 31;
    int warpId = (blockIdx.x * blockDim.x + threadIdx.x) >> 5;
    int nwarp = (gridDim.x * blockDim.x) >> 5;
    for (int e0 = warpId * 32; e0 < E; e0 += nwarp * 32) {
        int e = e0 + lane;
        bool pass = false;
        int s = 0, bin = 0;
        if (e < E) {
            int sid = g_s1id[edst[e]];
            if (sid >= 0) {
                pass = true;
                s = esrc[e];
                bin = etyp[e] * S1MAX + sid;
            }
        }
        unsigned mask = __ballot_sync(0xffffffffu, pass);
        while (mask) {
            int src_lane = __ffs(mask) - 1;
            mask &= mask - 1;
            int ss = __shfl_sync(0xffffffffu, s, src_lane);
            int bb = __shfl_sync(0xffffffffu, bin, src_lane);
            if (lane == 0) atomicAdd(&g_cnt1[bb], 1);
            float4 v = *(const float4*)&x[(size_t)ss * FDIM + lane * 4];
            red_add_v4(&g_agg1[(size_t)bb * FDIM + lane * 4], v);
        }
    }
}

// ---------------- k5: mma.sync fp16-split GEMM1 (2 passes) ----------------
// h1 = relu([agg1/c | x] @ [Wrel1;Wroot1] + b1)
// Per CTA: BM=128, N=128, K=512 in 8 groups of 64. Double-buffered (2 x 48KB).
#define SM5_BUF 49152
#define SM5_AHI 0
#define SM5_ALO 16384
#define SM5_B   32768
#define SM5_TOTAL (2 * SM5_BUF)

__global__ __launch_bounds__(256) void k5_mma(const float* __restrict__ x,
                                              const float* __restrict__ bias) {
    extern __shared__ char smem[];
    int M = g_s1count; if (M > S1MAX) M = S1MAX;
    int row0 = blockIdx.x * 128;
    if (row0 >= M) return;
    uint32_t sb = smem_u32(smem);
    int tid = threadIdx.x;
    int wid = tid >> 5;
    int lane = tid & 31;
    int wm = wid >> 1;          // 0..3  (warp m tile: 32 rows)
    int wn = wid & 1;           // 0..1  (warp n tile: 64 cols)

    int row  = tid >> 1;        // 0..127 (loader row)
    int half = tid & 1;         // cols half*32..+32 of the 64-chunk
    int gi = row0 + row;
    bool valid = gi < M;
    int gR = valid ? gi : 0;
    int anode = valid ? g_s1nodes[gR] : 0;

    float4 va[8];
    // ---- group A load into regs ----
    auto loadA = [&](int g) {
        const float* src;
        float inv = 1.0f;
        if (g < 6) {
            int seg = g >> 1;
            src = &g_agg1[((size_t)(seg * S1MAX + gR)) * FDIM + (g & 1) * 64 + half * 32];
            int c = g_cnt1[seg * S1MAX + gR];
            inv = 1.0f / (float)(c > 1 ? c : 1);
        } else {
            src = &x[(size_t)anode * FDIM + (g - 6) * 64 + half * 32];
        }
#pragma unroll
        for (int j = 0; j < 8; j++) {
            float4 v = make_float4(0.f, 0.f, 0.f, 0.f);
            if (valid) {
                v = *(const float4*)&src[j * 4];
                if (g < 6) { v.x *= inv; v.y *= inv; v.z *= inv; v.w *= inv; }
            }
            va[j] = v;
        }
    };
    // ---- convert + STS A hi/lo (fp16) ----
    auto stsA = [&](int buf) {
#pragma unroll
        for (int j = 0; j < 8; j++) {
            float4 v = va[j];
            __half2 h01 = __floats2half2_rn(v.x, v.y);
            __half2 h23 = __floats2half2_rn(v.z, v.w);
            float2 f01 = __half22float2(h01);
            float2 f23 = __half22float2(h23);
            __half2 l01 = __floats2half2_rn(v.x - f01.x, v.y - f01.y);
            __half2 l23 = __floats2half2_rn(v.z - f23.x, v.w - f23.y);
            uint32_t off = sw128(row * 128 + (half * 32 + j * 4) * 2);
            uint2 ph, pl;
            ph.x = *(uint32_t*)&h01; ph.y = *(uint32_t*)&h23;
            pl.x = *(uint32_t*)&l01; pl.y = *(uint32_t*)&l23;
            *(uint2*)(smem + buf * SM5_BUF + SM5_AHI + off) = ph;
            *(uint2*)(smem + buf * SM5_BUF + SM5_ALO + off) = pl;
        }
    };
    // ---- cp.async B tile (single fp16) ----
    auto cpB = [&](int g, int buf) {
        uint32_t base = sb + buf * SM5_BUF;
        const unsigned short* sW = &g_Wt1[row * 512 + g * 64 + half * 32];
#pragma unroll
        for (int j = 0; j < 4; j++) {
            uint32_t off = sw128(row * 128 + (half * 32 + j * 8) * 2);
            cp_async16(base + SM5_B + off, sW + j * 8);
        }
        CP_COMMIT();
    };

    float acc[2][8][4];
#pragma unroll
    for (int mt = 0; mt < 2; mt++)
#pragma unroll
        for (int n8 = 0; n8 < 8; n8++)
#pragma unroll
            for (int q = 0; q < 4; q++) acc[mt][n8][q] = 0.f;

    // prologue: group 0
    cpB(0, 0);
    loadA(0);
    stsA(0);
    CP_WAIT0();
    __syncthreads();

    for (int g = 0; g < 8; g++) {
        int cur = g & 1, nxt = cur ^ 1;
        if (g < 7) { cpB(g + 1, nxt); loadA(g + 1); }
        uint32_t bufb = sb + cur * SM5_BUF;
#pragma unroll
        for (int pass = 0; pass < 2; pass++) {
            uint32_t ab = bufb + ((pass == 1) ? SM5_ALO : SM5_AHI);
            uint32_t bb = bufb + SM5_B;
#pragma unroll
            for (int ks = 0; ks < 4; ks++) {
                uint32_t af[2][4];
#pragma unroll
                for (int mt = 0; mt < 2; mt++) {
                    int r = wm * 32 + mt * 16 + (lane & 7) + ((lane >> 3) & 1) * 8;
                    int cB = ks * 32 + (lane >> 4) * 16;
                    ldsm4(af[mt], ab + sw128(r * 128 + cB));
                }
                uint32_t bf[4][4];
#pragma unroll
                for (int nt = 0; nt < 4; nt++) {
                    int rn = wn * 64 + nt * 16 + (lane & 7) + (lane >> 4) * 8;
                    int cB = ks * 32 + ((lane >> 3) & 1) * 16;
                    ldsm4(bf[nt], bb + sw128(rn * 128 + cB));
                }
#pragma unroll
                for (int mt = 0; mt < 2; mt++)
#pragma unroll
                    for (int n8 = 0; n8 < 8; n8++)
                        mma16816(acc[mt][n8], af[mt], &bf[n8 >> 1][(n8 & 1) * 2]);
            }
        }
        if (g < 7) {
            stsA(nxt);
            CP_WAIT0();
            __syncthreads();
        }
    }

    // ---- epilogue: +bias, relu, store ----
#pragma unroll
    for (int mt = 0; mt < 2; mt++) {
#pragma unroll
        for (int n8 = 0; n8 < 8; n8++) {
            int r = row0 + wm * 32 + mt * 16 + (lane >> 2);
            int col = wn * 64 + n8 * 8 + (lane & 3) * 2;
            float2 bv = *(const float2*)&bias[col];
            if (r < M) {
                float2 o;
                o.x = fmaxf(acc[mt][n8][0] + bv.x, 0.f);
                o.y = fmaxf(acc[mt][n8][1] + bv.y, 0.f);
                *(float2*)&g_h1[(size_t)r * HDIM + col] = o;
            }
            if (r + 8 < M) {
                float2 o;
                o.x = fmaxf(acc[mt][n8][2] + bv.x, 0.f);
                o.y = fmaxf(acc[mt][n8][3] + bv.y, 0.f);
                *(float2*)&g_h1[(size_t)(r + 8) * HDIM + col] = o;
            }
        }
    }
}

// ---------------- k6: layer-2 edge aggregation (compacted edges) ------------
__global__ void k6_agg2() {
    int n2 = g_e2count; if (n2 > E2MAX) n2 = E2MAX;
    int w = (blockIdx.x * blockDim.x + threadIdx.x) >> 5;
    int lane = threadIdx.x & 31;
    int nw = (gridDim.x * blockDim.x) >> 5;
    for (int i = w; i < n2; i += nw) {
        int s = g_e2src[i];
        int bin = g_e2bin[i];
        int sid = g_s1id[s];
        if (sid < 0) continue;  // safety
        float4 v = *(const float4*)&g_h1[(size_t)sid * HDIM + lane * 4];
        red_add_v4(&g_agg2[(size_t)bin * HDIM + lane * 4], v);
    }
}

// ---------------- k7: GEMM2: node = [agg2/c | h1_T] @ [Wrel2;Wroot2] + b2 ----
__global__ __launch_bounds__(256) void k7_gemm_node(
    const float* __restrict__ Wrel, const float* __restrict__ Wroot,
    const float* __restrict__ bias) {
    int M = g_tcount; if (M > TMAXC) M = TMAXC;
    int row0 = blockIdx.x * 64;
    if (row0 >= M) return;
    __shared__ __align__(16) float As[16][64];
    __shared__ __align__(16) float Bs[16][64];
    int tid = threadIdx.x;
    int rg = tid >> 4;
    int cg = tid & 15;
    float acc[4][4];
#pragma unroll
    for (int m = 0; m < 4; m++)
#pragma unroll
        for (int n = 0; n < 4; n++) acc[m][n] = 0.f;

    int a_i = tid >> 2;
    int a_kk = (tid & 3) * 4;
    int gi = row0 + a_i;
    int hsrc = (gi < M) ? g_t2s1[gi] : 0;

    for (int kt = 0; kt < 32; kt++) {
        int k0 = kt * 16;
        float4 av = make_float4(0.f, 0.f, 0.f, 0.f);
        if (gi < M) {
            int k = k0 + a_kk;
            int seg = k >> 7;
            if (seg < 3) {
                av = *(const float4*)&g_agg2[((size_t)(seg * TMAXC + gi)) * HDIM + (k & 127)];
                int c = g_cnt2[seg * TMAXC + gi];
                float inv = 1.0f / (float)(c > 1 ? c : 1);
                av.x *= inv; av.y *= inv; av.z *= inv; av.w *= inv;
            } else {
                av = *(const float4*)&g_h1[(size_t)hsrc * HDIM + (k - 384)];
            }
        }
        As[a_kk + 0][a_i] = av.x;
        As[a_kk + 1][a_i] = av.y;
        As[a_kk + 2][a_i] = av.z;
        As[a_kk + 3][a_i] = av.w;
        {
            int kk = tid >> 4, col = (tid & 15) * 4;
            int k = k0 + kk;
            const float* srcp = (k < 384) ? &Wrel[(size_t)k * EDIM + col]
                                          : &Wroot[(size_t)(k - 384) * EDIM + col];
            *(float4*)&Bs[kk][col] = *(const float4*)srcp;
        }
        __syncthreads();
#pragma unroll
        for (int kk = 0; kk < 16; kk++) {
            float4 ta = *(float4*)&As[kk][rg * 4];
            float a4[4] = {ta.x, ta.y, ta.z, ta.w};
            float4 bb = *(float4*)&Bs[kk][cg * 4];
            float b4[4] = {bb.x, bb.y, bb.z, bb.w};
#pragma unroll
            for (int m = 0; m < 4; m++)
#pragma unroll
                for (int n = 0; n < 4; n++) acc[m][n] += a4[m] * b4[n];
        }
        __syncthreads();
    }
    float4 bv = *(const float4*)&bias[cg * 4];
#pragma unroll
    for (int m = 0; m < 4; m++) {
        int row = row0 + rg * 4 + m;
        if (row < M) {
            float4 o;
            o.x = acc[m][0] + bv.x;
            o.y = acc[m][1] + bv.y;
            o.z = acc[m][2] + bv.z;
            o.w = acc[m][3] + bv.w;
            *(float4*)&g_node[(size_t)row * EDIM + cg * 4] = o;
        }
    }
}

// ---------------- k8: out = tanh([node[nest]|node[food]] @ fc_W + fc_b) ------
__global__ void k8_final(const int* __restrict__ nest, const int* __restrict__ food,
                         const float* __restrict__ fcW, const float* __restrict__ fcb,
                         float* __restrict__ out) {
    __shared__ float pr[128];
    int b = blockIdx.x;
    int h = threadIdx.x;    // 0..127
    if (h < 64) {
        int tn = g_tid[nest[b]];
        pr[h] = g_node[tn * EDIM + h];
    } else {
        int tf = g_tid[food[b]];
        pr[h] = g_node[tf * EDIM + (h - 64)];
    }
    __syncthreads();
    float acc = fcb[h];
#pragma unroll 8
    for (int k = 0; k < 128; k++) acc = fmaf(pr[k], fcW[k * HDIM + h], acc);
    out[(size_t)b * HDIM + h] = tanhf(acc);
}

// ---------------- launch ----------------
extern "C" void kernel_launch(void* const* d_in, const int* in_sizes, int n_in,
                              void* d_out, int out_size) {
    const float* x      = (const float*)d_in[0];
    const int*   esrc   = (const int*)d_in[1];
    const int*   edst   = (const int*)d_in[2];
    const int*   etyp   = (const int*)d_in[3];
    // d_in[4] = edge_attr (unused by the reference output)
    const int*   nest   = (const int*)d_in[5];
    const int*   food   = (const int*)d_in[6];
    const float* Wrel1  = (const float*)d_in[7];
    const float* Wroot1 = (const float*)d_in[8];
    const float* b1     = (const float*)d_in[9];
    const float* Wrel2  = (const float*)d_in[10];
    const float* Wroot2 = (const float*)d_in[11];
    const float* b2     = (const float*)d_in[12];
    const float* fcW    = (const float*)d_in[13];
    const float* fcb    = (const float*)d_in[14];
    float* out = (float*)d_out;

    int N = in_sizes[0] / FDIM;
    int E = in_sizes[1];
    int B = in_sizes[5];

    cudaFuncSetAttribute(k5_mma, cudaFuncAttributeMaxDynamicSharedMemorySize, SM5_TOTAL);

    int scanBlocks = (E + 255) / 256;

    k0_init<<<1024, 256>>>(N, Wrel1, Wroot1);
    k1_targets<<<(2 * B + 255) / 256, 256>>>(nest, food, B);
    k2_scan<<<scanBlocks + ZERO_BLOCKS, 256>>>(esrc, edst, etyp, E, scanBlocks);
    k4_agg1<<<4736, 256>>>(esrc, edst, etyp, x, E);
    k5_mma<<<S1MAX / 128, 256, SM5_TOTAL>>>(x, b1);
    k6_agg2<<<2048, 256>>>();
    k7_gemm_node<<<TMAXC / 64, 256>>>(Wrel2, Wroot2, b2);
    k8_final<<<B, 128>>>(nest, food, fcW, fcb, out);
}

// round 12
// speedup vs baseline: 1.1155x; 1.0612x over previous
#include <cuda_runtime.h>
#include <cuda_fp16.h>
#include <cstdint>

// ---------------- problem constants (fixed shapes) ----------------
#define NMAX   100000
#define FDIM   128
#define HDIM   128
#define EDIM   64
#define RREL   3
#define TMAXC  2048      // max unique targets (2*B)
#define S1MAX  49152     // max |S1| (expected ~30K)
#define E2MAX  131072    // max layer-2 edges (expected ~33K)

#define ZERO_BLOCKS 2048

// ---------------- device scratch (static, no allocation) ----------------
__device__ int   g_tid[NMAX];       // node -> target compact id (-1 none)
__device__ int   g_s1id[NMAX];      // node -> S1 compact id (-1 none)
__device__ int   g_tnodes[TMAXC];
__device__ int   g_t2s1[TMAXC];     // target idx -> s1 idx
__device__ int   g_s1nodes[S1MAX];
__device__ int   g_tcount;
__device__ int   g_s1count;
__device__ int   g_e2count;
__device__ int   g_e2src[E2MAX];
__device__ int   g_e2bin[E2MAX];
__device__ float g_agg1[(size_t)RREL * S1MAX * FDIM];   // ~75.5 MB
__device__ int   g_cnt1[RREL * S1MAX];
__device__ float g_h1[(size_t)S1MAX * HDIM];            // ~25 MB
__device__ float g_agg2[RREL * TMAXC * HDIM];
__device__ int   g_cnt2[RREL * TMAXC];
__device__ float g_node[TMAXC * EDIM];
// transposed fp16 layer-1 weights: [N=128][K=512]
__device__ __align__(16) unsigned short g_Wt1[HDIM * 512];
// fp16 copy of x for the edge-aggregation pass: [NMAX][FDIM]
__device__ __align__(16) unsigned short g_xh[(size_t)NMAX * FDIM];

__device__ __forceinline__ void red_add_v4(float* p, float4 v) {
    asm volatile("red.global.add.v4.f32 [%0], {%1,%2,%3,%4};"
                 :: "l"(p), "f"(v.x), "f"(v.y), "f"(v.z), "f"(v.w) : "memory");
}

__device__ __forceinline__ uint32_t smem_u32(const void* p) {
    uint32_t a;
    asm("{ .reg .u64 t; cvta.to.shared.u64 t, %1; cvt.u32.u64 %0, t; }"
        : "=r"(a) : "l"(p));
    return a;
}
__device__ __forceinline__ uint32_t sw128(uint32_t off) {
    return off ^ ((off >> 3) & 0x70);
}
__device__ __forceinline__ void ldsm4(uint32_t r[4], uint32_t addr) {
    asm volatile("ldmatrix.sync.aligned.m8n8.x4.shared.b16 {%0,%1,%2,%3}, [%4];"
                 : "=r"(r[0]), "=r"(r[1]), "=r"(r[2]), "=r"(r[3]) : "r"(addr));
}
__device__ __forceinline__ void mma16816(float* c, const uint32_t* a, const uint32_t* b) {
    asm volatile(
        "mma.sync.aligned.m16n8k16.row.col.f32.f16.f16.f32 "
        "{%0,%1,%2,%3}, {%4,%5,%6,%7}, {%8,%9}, {%0,%1,%2,%3};"
        : "+f"(c[0]), "+f"(c[1]), "+f"(c[2]), "+f"(c[3])
        : "r"(a[0]), "r"(a[1]), "r"(a[2]), "r"(a[3]), "r"(b[0]), "r"(b[1]));
}
__device__ __forceinline__ void cp_async16(uint32_t smem_dst, const void* gsrc) {
    asm volatile("cp.async.ca.shared.global [%0], [%1], 16;"
                 :: "r"(smem_dst), "l"(gsrc) : "memory");
}
#define CP_COMMIT() asm volatile("cp.async.commit_group;" ::: "memory")
#define CP_WAIT0()  asm volatile("cp.async.wait_group 0;" ::: "memory")

// ---------------- k0: init maps/counters + weight transpose + x->fp16 --------
__global__ void k0_init(int N, const float* __restrict__ Wrel,
                        const float* __restrict__ Wroot,
                        const float* __restrict__ x) {
    int i = blockIdx.x * blockDim.x + threadIdx.x;
    int stride = gridDim.x * blockDim.x;
    for (int j = i; j < N; j += stride) { g_tid[j] = -1; g_s1id[j] = -1; }
    for (int j = i; j < RREL * S1MAX; j += stride) g_cnt1[j] = 0;
    for (int j = i; j < RREL * TMAXC; j += stride) g_cnt2[j] = 0;
    for (int j = i; j < RREL * TMAXC * HDIM; j += stride) g_agg2[j] = 0.f;
    for (int j = i; j < HDIM * 512; j += stride) {
        int n = j >> 9;
        int k = j & 511;
        float v = (k < 384) ? Wrel[(size_t)k * HDIM + n]
                            : Wroot[(size_t)(k - 384) * HDIM + n];
        g_Wt1[j] = __half_as_ushort(__float2half_rn(v));
    }
    // x -> fp16 (half2 per iteration)
    int nh2 = N * (FDIM / 2);
    for (int j = i; j < nh2; j += stride) {
        float2 v = *(const float2*)&x[(size_t)j * 2];
        __half2 h = __floats2half2_rn(v.x, v.y);
        *(uint32_t*)&g_xh[(size_t)j * 2] = *(uint32_t*)&h;
    }
    if (i == 0) { g_tcount = 0; g_s1count = 0; g_e2count = 0; }
}

// ---------------- k1: mark target set T = nest ∪ food ----------------
__global__ void k1_targets(const int* __restrict__ nest,
                           const int* __restrict__ food, int B) {
    int i = blockIdx.x * blockDim.x + threadIdx.x;
    if (i >= 2 * B) return;
    int v = (i < B) ? nest[i] : food[i - B];
    if (atomicCAS(&g_tid[v], -1, -2) == -1) {
        int id = atomicAdd(&g_tcount, 1);       // <= 2*B <= TMAXC
        g_tnodes[id] = v;
        int sid = atomicAdd(&g_s1count, 1);
        g_s1nodes[sid] = v;
        g_s1id[v] = sid;
        g_t2s1[id] = sid;
        g_tid[v] = id;
    }
}

// ---------------- k2: fused edge scan (dst∈T, build S1) + agg1 zeroing --------
__global__ void k2_scan(const int* __restrict__ esrc, const int* __restrict__ edst,
                        const int* __restrict__ etyp, int E, int scanBlocks) {
    if ((int)blockIdx.x >= scanBlocks) {
        // ---- zero role ----
        const size_t per4 = (size_t)RREL * S1MAX * (FDIM / 4);
        float4* base = (float4*)g_agg1;
        float4 z = make_float4(0.f, 0.f, 0.f, 0.f);
        size_t start = (size_t)(blockIdx.x - scanBlocks) * blockDim.x + threadIdx.x;
        size_t stride = (size_t)ZERO_BLOCKS * blockDim.x;
        for (size_t j = start; j < per4; j += stride) base[j] = z;
        return;
    }
    // ---- scan role ----
    int e = blockIdx.x * blockDim.x + threadIdx.x;
    bool pass = false;
    int td = -1;
    if (e < E) {
        td = g_tid[edst[e]];
        pass = (td >= 0);
    }
    unsigned mask = __ballot_sync(0xffffffffu, pass);
    if (!pass) return;
    int t = etyp[e];
    int s = esrc[e];
    int lane = threadIdx.x & 31;
    int leader = __ffs(mask) - 1;
    int rank = __popc(mask & ((1u << lane) - 1));
    int base = 0;
    if (lane == leader) base = atomicAdd(&g_e2count, __popc(mask));
    base = __shfl_sync(mask, base, leader);
    int idx = base + rank;
    int bin = t * TMAXC + td;
    atomicAdd(&g_cnt2[bin], 1);
    if (idx < E2MAX) { g_e2src[idx] = s; g_e2bin[idx] = bin; }
    if (atomicCAS(&g_s1id[s], -1, -2) == -1) {
        int id = atomicAdd(&g_s1count, 1);
        if (id < S1MAX) { g_s1nodes[id] = s; g_s1id[s] = id; }
    }
}

// ---------------- k4: layer-1 aggregation, single pass, fp16 x reads ---------
__global__ void k4_agg1(const int* __restrict__ esrc, const int* __restrict__ edst,
                        const int* __restrict__ etyp, int E) {
    int lane = threadIdx.x & 31;
    int warpId = (blockIdx.x * blockDim.x + threadIdx.x) >> 5;
    int nwarp = (gridDim.x * blockDim.x) >> 5;
    for (int e0 = warpId * 32; e0 < E; e0 += nwarp * 32) {
        int e = e0 + lane;
        bool pass = false;
        int s = 0, bin = 0;
        if (e < E) {
            int sid = g_s1id[edst[e]];
            if (sid >= 0) {
                pass = true;
                s = esrc[e];
                bin = etyp[e] * S1MAX + sid;
            }
        }
        unsigned mask = __ballot_sync(0xffffffffu, pass);
        while (mask) {
            int src_lane = __ffs(mask) - 1;
            mask &= mask - 1;
            int ss = __shfl_sync(0xffffffffu, s, src_lane);
            int bb = __shfl_sync(0xffffffffu, bin, src_lane);
            if (lane == 0) atomicAdd(&g_cnt1[bb], 1);
            uint2 u = *(const uint2*)&g_xh[(size_t)ss * FDIM + lane * 4];
            __half2 h0 = *(__half2*)&u.x;
            __half2 h1 = *(__half2*)&u.y;
            float2 f0 = __half22float2(h0);
            float2 f1 = __half22float2(h1);
            float4 v = make_float4(f0.x, f0.y, f1.x, f1.y);
            red_add_v4(&g_agg1[(size_t)bb * FDIM + lane * 4], v);
        }
    }
}

// ---------------- k5: mma.sync fp16 GEMM1 (single pass) ----------------
// h1 = relu([agg1/c | x] @ [Wrel1;Wroot1] + b1)
// Per CTA: BM=128, N=128, K=512 in 8 groups of 64. Double-buffered (2 x 32KB)
// -> 2 CTAs/SM, single wave.
#define SM5_BUF 32768
#define SM5_A   0
#define SM5_B   16384
#define SM5_TOTAL (2 * SM5_BUF)

__global__ __launch_bounds__(256) void k5_mma(const float* __restrict__ x,
                                              const float* __restrict__ bias) {
    extern __shared__ char smem[];
    int M = g_s1count; if (M > S1MAX) M = S1MAX;
    int row0 = blockIdx.x * 128;
    if (row0 >= M) return;
    uint32_t sb = smem_u32(smem);
    int tid = threadIdx.x;
    int wid = tid >> 5;
    int lane = tid & 31;
    int wm = wid >> 1;          // 0..3  (warp m tile: 32 rows)
    int wn = wid & 1;           // 0..1  (warp n tile: 64 cols)

    int row  = tid >> 1;        // 0..127 (loader row)
    int half = tid & 1;         // cols half*32..+32 of the 64-chunk
    int gi = row0 + row;
    bool valid = gi < M;
    int gR = valid ? gi : 0;
    int anode = valid ? g_s1nodes[gR] : 0;

    float4 va[8];
    // ---- group A load into regs ----
    auto loadA = [&](int g) {
        const float* src;
        float inv = 1.0f;
        if (g < 6) {
            int seg = g >> 1;
            src = &g_agg1[((size_t)(seg * S1MAX + gR)) * FDIM + (g & 1) * 64 + half * 32];
            int c = g_cnt1[seg * S1MAX + gR];
            inv = 1.0f / (float)(c > 1 ? c : 1);
        } else {
            src = &x[(size_t)anode * FDIM + (g - 6) * 64 + half * 32];
        }
#pragma unroll
        for (int j = 0; j < 8; j++) {
            float4 v = make_float4(0.f, 0.f, 0.f, 0.f);
            if (valid) {
                v = *(const float4*)&src[j * 4];
                if (g < 6) { v.x *= inv; v.y *= inv; v.z *= inv; v.w *= inv; }
            }
            va[j] = v;
        }
    };
    // ---- convert + STS A (fp16) ----
    auto stsA = [&](int buf) {
#pragma unroll
        for (int j = 0; j < 8; j++) {
            float4 v = va[j];
            __half2 h01 = __floats2half2_rn(v.x, v.y);
            __half2 h23 = __floats2half2_rn(v.z, v.w);
            uint32_t off = sw128(row * 128 + (half * 32 + j * 4) * 2);
            uint2 ph;
            ph.x = *(uint32_t*)&h01; ph.y = *(uint32_t*)&h23;
            *(uint2*)(smem + buf * SM5_BUF + SM5_A + off) = ph;
        }
    };
    // ---- cp.async B tile (fp16) ----
    auto cpB = [&](int g, int buf) {
        uint32_t base = sb + buf * SM5_BUF;
        const unsigned short* sW = &g_Wt1[row * 512 + g * 64 + half * 32];
#pragma unroll
        for (int j = 0; j < 4; j++) {
            uint32_t off = sw128(row * 128 + (half * 32 + j * 8) * 2);
            cp_async16(base + SM5_B + off, sW + j * 8);
        }
        CP_COMMIT();
    };

    float acc[2][8][4];
#pragma unroll
    for (int mt = 0; mt < 2; mt++)
#pragma unroll
        for (int n8 = 0; n8 < 8; n8++)
#pragma unroll
            for (int q = 0; q < 4; q++) acc[mt][n8][q] = 0.f;

    // prologue: group 0
    cpB(0, 0);
    loadA(0);
    stsA(0);
    CP_WAIT0();
    __syncthreads();

    for (int g = 0; g < 8; g++) {
        int cur = g & 1, nxt = cur ^ 1;
        if (g < 7) { cpB(g + 1, nxt); loadA(g + 1); }
        uint32_t bufb = sb + cur * SM5_BUF;
        uint32_t ab = bufb + SM5_A;
        uint32_t bb = bufb + SM5_B;
#pragma unroll
        for (int ks = 0; ks < 4; ks++) {
            uint32_t af[2][4];
#pragma unroll
            for (int mt = 0; mt < 2; mt++) {
                int r = wm * 32 + mt * 16 + (lane & 7) + ((lane >> 3) & 1) * 8;
                int cB = ks * 32 + (lane >> 4) * 16;
                ldsm4(af[mt], ab + sw128(r * 128 + cB));
            }
            uint32_t bf[4][4];
#pragma unroll
            for (int nt = 0; nt < 4; nt++) {
                int rn = wn * 64 + nt * 16 + (lane & 7) + (lane >> 4) * 8;
                int cB = ks * 32 + ((lane >> 3) & 1) * 16;
                ldsm4(bf[nt], bb + sw128(rn * 128 + cB));
            }
#pragma unroll
            for (int mt = 0; mt < 2; mt++)
#pragma unroll
                for (int n8 = 0; n8 < 8; n8++)
                    mma16816(acc[mt][n8], af[mt], &bf[n8 >> 1][(n8 & 1) * 2]);
        }
        if (g < 7) {
            stsA(nxt);
            CP_WAIT0();
            __syncthreads();
        }
    }

    // ---- epilogue: +bias, relu, store ----
#pragma unroll
    for (int mt = 0; mt < 2; mt++) {
#pragma unroll
        for (int n8 = 0; n8 < 8; n8++) {
            int r = row0 + wm * 32 + mt * 16 + (lane >> 2);
            int col = wn * 64 + n8 * 8 + (lane & 3) * 2;
            float2 bv = *(const float2*)&bias[col];
            if (r < M) {
                float2 o;
                o.x = fmaxf(acc[mt][n8][0] + bv.x, 0.f);
                o.y = fmaxf(acc[mt][n8][1] + bv.y, 0.f);
                *(float2*)&g_h1[(size_t)r * HDIM + col] = o;
            }
            if (r + 8 < M) {
                float2 o;
                o.x = fmaxf(acc[mt][n8][2] + bv.x, 0.f);
                o.y = fmaxf(acc[mt][n8][3] + bv.y, 0.f);
                *(float2*)&g_h1[(size_t)(r + 8) * HDIM + col] = o;
            }
        }
    }
}

// ---------------- k6: layer-2 edge aggregation (compacted edges) ------------
__global__ void k6_agg2() {
    int n2 = g_e2count; if (n2 > E2MAX) n2 = E2MAX;
    int w = (blockIdx.x * blockDim.x + threadIdx.x) >> 5;
    int lane = threadIdx.x & 31;
    int nw = (gridDim.x * blockDim.x) >> 5;
    for (int i = w; i < n2; i += nw) {
        int s = g_e2src[i];
        int bin = g_e2bin[i];
        int sid = g_s1id[s];
        if (sid < 0) continue;  // safety
        float4 v = *(const float4*)&g_h1[(size_t)sid * HDIM + lane * 4];
        red_add_v4(&g_agg2[(size_t)bin * HDIM + lane * 4], v);
    }
}

// ---------------- k7: GEMM2: node = [agg2/c | h1_T] @ [Wrel2;Wroot2] + b2 ----
__global__ __launch_bounds__(256) void k7_gemm_node(
    const float* __restrict__ Wrel, const float* __restrict__ Wroot,
    const float* __restrict__ bias) {
    int M = g_tcount; if (M > TMAXC) M = TMAXC;
    int row0 = blockIdx.x * 64;
    if (row0 >= M) return;
    __shared__ __align__(16) float As[16][64];
    __shared__ __align__(16) float Bs[16][64];
    int tid = threadIdx.x;
    int rg = tid >> 4;
    int cg = tid & 15;
    float acc[4][4];
#pragma unroll
    for (int m = 0; m < 4; m++)
#pragma unroll
        for (int n = 0; n < 4; n++) acc[m][n] = 0.f;

    int a_i = tid >> 2;
    int a_kk = (tid & 3) * 4;
    int gi = row0 + a_i;
    int hsrc = (gi < M) ? g_t2s1[gi] : 0;

    for (int kt = 0; kt < 32; kt++) {
        int k0 = kt * 16;
        float4 av = make_float4(0.f, 0.f, 0.f, 0.f);
        if (gi < M) {
            int k = k0 + a_kk;
            int seg = k >> 7;
            if (seg < 3) {
                av = *(const float4*)&g_agg2[((size_t)(seg * TMAXC + gi)) * HDIM + (k & 127)];
                int c = g_cnt2[seg * TMAXC + gi];
                float inv = 1.0f / (float)(c > 1 ? c : 1);
                av.x *= inv; av.y *= inv; av.z *= inv; av.w *= inv;
            } else {
                av = *(const float4*)&g_h1[(size_t)hsrc * HDIM + (k - 384)];
            }
        }
        As[a_kk + 0][a_i] = av.x;
        As[a_kk + 1][a_i] = av.y;
        As[a_kk + 2][a_i] = av.z;
        As[a_kk + 3][a_i] = av.w;
        {
            int kk = tid >> 4, col = (tid & 15) * 4;
            int k = k0 + kk;
            const float* srcp = (k < 384) ? &Wrel[(size_t)k * EDIM + col]
                                          : &Wroot[(size_t)(k - 384) * EDIM + col];
            *(float4*)&Bs[kk][col] = *(const float4*)srcp;
        }
        __syncthreads();
#pragma unroll
        for (int kk = 0; kk < 16; kk++) {
            float4 ta = *(float4*)&As[kk][rg * 4];
            float a4[4] = {ta.x, ta.y, ta.z, ta.w};
            float4 bb = *(float4*)&Bs[kk][cg * 4];
            float b4[4] = {bb.x, bb.y, bb.z, bb.w};
#pragma unroll
            for (int m = 0; m < 4; m++)
#pragma unroll
                for (int n = 0; n < 4; n++) acc[m][n] += a4[m] * b4[n];
        }
        __syncthreads();
    }
    float4 bv = *(const float4*)&bias[cg * 4];
#pragma unroll
    for (int m = 0; m < 4; m++) {
        int row = row0 + rg * 4 + m;
        if (row < M) {
            float4 o;
            o.x = acc[m][0] + bv.x;
            o.y = acc[m][1] + bv.y;
            o.z = acc[m][2] + bv.z;
            o.w = acc[m][3] + bv.w;
            *(float4*)&g_node[(size_t)row * EDIM + cg * 4] = o;
        }
    }
}

// ---------------- k8: out = tanh([node[nest]|node[food]] @ fc_W + fc_b) ------
__global__ void k8_final(const int* __restrict__ nest, const int* __restrict__ food,
                         const float* __restrict__ fcW, const float* __restrict__ fcb,
                         float* __restrict__ out) {
    __shared__ float pr[128];
    int b = blockIdx.x;
    int h = threadIdx.x;    // 0..127
    if (h < 64) {
        int tn = g_tid[nest[b]];
        pr[h] = g_node[tn * EDIM + h];
    } else {
        int tf = g_tid[food[b]];
        pr[h] = g_node[tf * EDIM + (h - 64)];
    }
    __syncthreads();
    float acc = fcb[h];
#pragma unroll 8
    for (int k = 0; k < 128; k++) acc = fmaf(pr[k], fcW[k * HDIM + h], acc);
    out[(size_t)b * HDIM + h] = tanhf(acc);
}

// ---------------- launch ----------------
extern "C" void kernel_launch(void* const* d_in, const int* in_sizes, int n_in,
                              void* d_out, int out_size) {
    const float* x      = (const float*)d_in[0];
    const int*   esrc   = (const int*)d_in[1];
    const int*   edst   = (const int*)d_in[2];
    const int*   etyp   = (const int*)d_in[3];
    // d_in[4] = edge_attr (unused by the reference output)
    const int*   nest   = (const int*)d_in[5];
    const int*   food   = (const int*)d_in[6];
    const float* Wrel1  = (const float*)d_in[7];
    const float* Wroot1 = (const float*)d_in[8];
    const float* b1     = (const float*)d_in[9];
    const float* Wrel2  = (const float*)d_in[10];
    const float* Wroot2 = (const float*)d_in[11];
    const float* b2     = (const float*)d_in[12];
    const float* fcW    = (const float*)d_in[13];
    const float* fcb    = (const float*)d_in[14];
    float* out = (float*)d_out;

    int N = in_sizes[0] / FDIM;
    int E = in_sizes[1];
    int B = in_sizes[5];

    cudaFuncSetAttribute(k5_mma, cudaFuncAttributeMaxDynamicSharedMemorySize, SM5_TOTAL);

    int scanBlocks = (E + 255) / 256;

    k0_init<<<1024, 256>>>(N, Wrel1, Wroot1, x);
    k1_targets<<<(2 * B + 255) / 256, 256>>>(nest, food, B);
    k2_scan<<<scanBlocks + ZERO_BLOCKS, 256>>>(esrc, edst, etyp, E, scanBlocks);
    k4_agg1<<<4736, 256>>>(esrc, edst, etyp, E);
    k5_mma<<<S1MAX / 128, 256, SM5_TOTAL>>>(x, b1);
    k6_agg2<<<2048, 256>>>();
    k7_gemm_node<<<TMAXC / 64, 256>>>(Wrel2, Wroot2, b2);
    k8_final<<<B, 128>>>(nest, food, fcW, fcb, out);
}

// round 13
// speedup vs baseline: 1.1331x; 1.0157x over previous
#include <cuda_runtime.h>
#include <cuda_fp16.h>
#include <cstdint>

// ---------------- problem constants (fixed shapes) ----------------
#define NMAX   100000
#define FDIM   128
#define HDIM   128
#define EDIM   64
#define RREL   3
#define TMAXC  2048      // max unique targets (2*B)
#define S1MAX  49152     // max |S1| (expected ~30K)
#define E2MAX  131072    // max layer-2 edges (expected ~33K)

#define ZERO_BLOCKS 2048

// ---------------- device scratch (static, no allocation) ----------------
__device__ int   g_tid[NMAX];       // node -> target compact id (-1 none)
__device__ int   g_s1id[NMAX];      // node -> S1 compact id (-1 none)
__device__ int   g_tnodes[TMAXC];
__device__ int   g_t2s1[TMAXC];     // target idx -> s1 idx
__device__ int   g_s1nodes[S1MAX];
__device__ int   g_tcount;
__device__ int   g_s1count;
__device__ int   g_e2count;
__device__ int   g_e2src[E2MAX];
__device__ int   g_e2bin[E2MAX];
// agg1 packed by node: [sid][RREL][FDIM] -> live prefix is dense (L2-resident)
__device__ float g_agg1[(size_t)S1MAX * RREL * FDIM];   // ~75.5 MB
__device__ int   g_cnt1[S1MAX * RREL];
__device__ float g_h1[(size_t)S1MAX * HDIM];            // ~25 MB
__device__ float g_agg2[RREL * TMAXC * HDIM];
__device__ int   g_cnt2[RREL * TMAXC];
__device__ float g_node[TMAXC * EDIM];
// transposed fp16 layer-1 weights: [N=128][K=512]
__device__ __align__(16) unsigned short g_Wt1[HDIM * 512];
// fp16 copy of x for the edge-aggregation pass: [NMAX][FDIM]
__device__ __align__(16) unsigned short g_xh[(size_t)NMAX * FDIM];

__device__ __forceinline__ void red_add_v4(float* p, float4 v) {
    asm volatile("red.global.add.v4.f32 [%0], {%1,%2,%3,%4};"
                 :: "l"(p), "f"(v.x), "f"(v.y), "f"(v.z), "f"(v.w) : "memory");
}

__device__ __forceinline__ uint32_t smem_u32(const void* p) {
    uint32_t a;
    asm("{ .reg .u64 t; cvta.to.shared.u64 t, %1; cvt.u32.u64 %0, t; }"
        : "=r"(a) : "l"(p));
    return a;
}
__device__ __forceinline__ uint32_t sw128(uint32_t off) {
    return off ^ ((off >> 3) & 0x70);
}
__device__ __forceinline__ void ldsm4(uint32_t r[4], uint32_t addr) {
    asm volatile("ldmatrix.sync.aligned.m8n8.x4.shared.b16 {%0,%1,%2,%3}, [%4];"
                 : "=r"(r[0]), "=r"(r[1]), "=r"(r[2]), "=r"(r[3]) : "r"(addr));
}
__device__ __forceinline__ void mma16816(float* c, const uint32_t* a, const uint32_t* b) {
    asm volatile(
        "mma.sync.aligned.m16n8k16.row.col.f32.f16.f16.f32 "
        "{%0,%1,%2,%3}, {%4,%5,%6,%7}, {%8,%9}, {%0,%1,%2,%3};"
        : "+f"(c[0]), "+f"(c[1]), "+f"(c[2]), "+f"(c[3])
        : "r"(a[0]), "r"(a[1]), "r"(a[2]), "r"(a[3]), "r"(b[0]), "r"(b[1]));
}
__device__ __forceinline__ void cp_async16(uint32_t smem_dst, const void* gsrc) {
    asm volatile("cp.async.ca.shared.global [%0], [%1], 16;"
                 :: "r"(smem_dst), "l"(gsrc) : "memory");
}
#define CP_COMMIT() asm volatile("cp.async.commit_group;" ::: "memory")
#define CP_WAIT0()  asm volatile("cp.async.wait_group 0;" ::: "memory")

// ---------------- k0: init maps/counters + weight transpose + x->fp16 --------
__global__ void k0_init(int N, const float* __restrict__ Wrel,
                        const float* __restrict__ Wroot,
                        const float* __restrict__ x) {
    int i = blockIdx.x * blockDim.x + threadIdx.x;
    int stride = gridDim.x * blockDim.x;
    for (int j = i; j < N; j += stride) { g_tid[j] = -1; g_s1id[j] = -1; }
    for (int j = i; j < RREL * S1MAX; j += stride) g_cnt1[j] = 0;
    for (int j = i; j < RREL * TMAXC; j += stride) g_cnt2[j] = 0;
    for (int j = i; j < RREL * TMAXC * HDIM; j += stride) g_agg2[j] = 0.f;
    for (int j = i; j < HDIM * 512; j += stride) {
        int n = j >> 9;
        int k = j & 511;
        float v = (k < 384) ? Wrel[(size_t)k * HDIM + n]
                            : Wroot[(size_t)(k - 384) * HDIM + n];
        g_Wt1[j] = __half_as_ushort(__float2half_rn(v));
    }
    // x -> fp16 (half2 per iteration)
    int nh2 = N * (FDIM / 2);
    for (int j = i; j < nh2; j += stride) {
        float2 v = *(const float2*)&x[(size_t)j * 2];
        __half2 h = __floats2half2_rn(v.x, v.y);
        *(uint32_t*)&g_xh[(size_t)j * 2] = *(uint32_t*)&h;
    }
    if (i == 0) { g_tcount = 0; g_s1count = 0; g_e2count = 0; }
}

// ---------------- k1: mark target set T = nest ∪ food ----------------
__global__ void k1_targets(const int* __restrict__ nest,
                           const int* __restrict__ food, int B) {
    int i = blockIdx.x * blockDim.x + threadIdx.x;
    if (i >= 2 * B) return;
    int v = (i < B) ? nest[i] : food[i - B];
    if (atomicCAS(&g_tid[v], -1, -2) == -1) {
        int id = atomicAdd(&g_tcount, 1);       // <= 2*B <= TMAXC
        g_tnodes[id] = v;
        int sid = atomicAdd(&g_s1count, 1);
        g_s1nodes[sid] = v;
        g_s1id[v] = sid;
        g_t2s1[id] = sid;
        g_tid[v] = id;
    }
}

// ---------------- k2: fused edge scan (dst∈T, build S1) + agg1 zeroing --------
__global__ void k2_scan(const int* __restrict__ esrc, const int* __restrict__ edst,
                        const int* __restrict__ etyp, int E, int scanBlocks) {
    if ((int)blockIdx.x >= scanBlocks) {
        // ---- zero role ----
        const size_t per4 = (size_t)RREL * S1MAX * (FDIM / 4);
        float4* base = (float4*)g_agg1;
        float4 z = make_float4(0.f, 0.f, 0.f, 0.f);
        size_t start = (size_t)(blockIdx.x - scanBlocks) * blockDim.x + threadIdx.x;
        size_t stride = (size_t)ZERO_BLOCKS * blockDim.x;
        for (size_t j = start; j < per4; j += stride) base[j] = z;
        return;
    }
    // ---- scan role ----
    int e = blockIdx.x * blockDim.x + threadIdx.x;
    bool pass = false;
    int td = -1;
    if (e < E) {
        td = g_tid[edst[e]];
        pass = (td >= 0);
    }
    unsigned mask = __ballot_sync(0xffffffffu, pass);
    if (!pass) return;
    int t = etyp[e];
    int s = esrc[e];
    int lane = threadIdx.x & 31;
    int leader = __ffs(mask) - 1;
    int rank = __popc(mask & ((1u << lane) - 1));
    int base = 0;
    if (lane == leader) base = atomicAdd(&g_e2count, __popc(mask));
    base = __shfl_sync(mask, base, leader);
    int idx = base + rank;
    int bin = t * TMAXC + td;
    atomicAdd(&g_cnt2[bin], 1);
    if (idx < E2MAX) { g_e2src[idx] = s; g_e2bin[idx] = bin; }
    if (atomicCAS(&g_s1id[s], -1, -2) == -1) {
        int id = atomicAdd(&g_s1count, 1);
        if (id < S1MAX) { g_s1nodes[id] = s; g_s1id[s] = id; }
    }
}

// ---------------- k4: layer-1 aggregation, packed bins (sid*RREL+t) ---------
__global__ void k4_agg1(const int* __restrict__ esrc, const int* __restrict__ edst,
                        const int* __restrict__ etyp, int E) {
    int lane = threadIdx.x & 31;
    int warpId = (blockIdx.x * blockDim.x + threadIdx.x) >> 5;
    int nwarp = (gridDim.x * blockDim.x) >> 5;
    for (int e0 = warpId * 32; e0 < E; e0 += nwarp * 32) {
        int e = e0 + lane;
        bool pass = false;
        int s = 0, bin = 0;
        if (e < E) {
            int sid = g_s1id[edst[e]];
            if (sid >= 0) {
                pass = true;
                s = esrc[e];
                bin = sid * RREL + etyp[e];
            }
        }
        unsigned mask = __ballot_sync(0xffffffffu, pass);
        while (mask) {
            int src_lane = __ffs(mask) - 1;
            mask &= mask - 1;
            int ss = __shfl_sync(0xffffffffu, s, src_lane);
            int bb = __shfl_sync(0xffffffffu, bin, src_lane);
            if (lane == 0) atomicAdd(&g_cnt1[bb], 1);
            uint2 u = *(const uint2*)&g_xh[(size_t)ss * FDIM + lane * 4];
            __half2 h0 = *(__half2*)&u.x;
            __half2 h1 = *(__half2*)&u.y;
            float2 f0 = __half22float2(h0);
            float2 f1 = __half22float2(h1);
            float4 v = make_float4(f0.x, f0.y, f1.x, f1.y);
            red_add_v4(&g_agg1[(size_t)bb * FDIM + lane * 4], v);
        }
    }
}

// ---------------- k5: mma.sync fp16 GEMM1 (single pass) ----------------
// h1 = relu([agg1/c | x] @ [Wrel1;Wroot1] + b1)
// Per CTA: BM=128, N=128, K=512 in 8 groups of 64. Double-buffered (2 x 32KB)
// -> 2 CTAs/SM, single wave.
#define SM5_BUF 32768
#define SM5_A   0
#define SM5_B   16384
#define SM5_TOTAL (2 * SM5_BUF)

__global__ __launch_bounds__(256) void k5_mma(const float* __restrict__ x,
                                              const float* __restrict__ bias) {
    extern __shared__ char smem[];
    int M = g_s1count; if (M > S1MAX) M = S1MAX;
    int row0 = blockIdx.x * 128;
    if (row0 >= M) return;
    uint32_t sb = smem_u32(smem);
    int tid = threadIdx.x;
    int wid = tid >> 5;
    int lane = tid & 31;
    int wm = wid >> 1;          // 0..3  (warp m tile: 32 rows)
    int wn = wid & 1;           // 0..1  (warp n tile: 64 cols)

    int row  = tid >> 1;        // 0..127 (loader row)
    int half = tid & 1;         // cols half*32..+32 of the 64-chunk
    int gi = row0 + row;
    bool valid = gi < M;
    int gR = valid ? gi : 0;
    int anode = valid ? g_s1nodes[gR] : 0;

    float4 va[8];
    // ---- group A load into regs (packed agg1 layout [sid][RREL][FDIM]) ----
    auto loadA = [&](int g) {
        const float* src;
        float inv = 1.0f;
        if (g < 6) {
            int seg = g >> 1;
            src = &g_agg1[((size_t)(gR * RREL + seg)) * FDIM + (g & 1) * 64 + half * 32];
            int c = g_cnt1[gR * RREL + seg];
            inv = 1.0f / (float)(c > 1 ? c : 1);
        } else {
            src = &x[(size_t)anode * FDIM + (g - 6) * 64 + half * 32];
        }
#pragma unroll
        for (int j = 0; j < 8; j++) {
            float4 v = make_float4(0.f, 0.f, 0.f, 0.f);
            if (valid) {
                v = *(const float4*)&src[j * 4];
                if (g < 6) { v.x *= inv; v.y *= inv; v.z *= inv; v.w *= inv; }
            }
            va[j] = v;
        }
    };
    // ---- convert + STS A (fp16) ----
    auto stsA = [&](int buf) {
#pragma unroll
        for (int j = 0; j < 8; j++) {
            float4 v = va[j];
            __half2 h01 = __floats2half2_rn(v.x, v.y);
            __half2 h23 = __floats2half2_rn(v.z, v.w);
            uint32_t off = sw128(row * 128 + (half * 32 + j * 4) * 2);
            uint2 ph;
            ph.x = *(uint32_t*)&h01; ph.y = *(uint32_t*)&h23;
            *(uint2*)(smem + buf * SM5_BUF + SM5_A + off) = ph;
        }
    };
    // ---- cp.async B tile (fp16) ----
    auto cpB = [&](int g, int buf) {
        uint32_t base = sb + buf * SM5_BUF;
        const unsigned short* sW = &g_Wt1[row * 512 + g * 64 + half * 32];
#pragma unroll
        for (int j = 0; j < 4; j++) {
            uint32_t off = sw128(row * 128 + (half * 32 + j * 8) * 2);
            cp_async16(base + SM5_B + off, sW + j * 8);
        }
        CP_COMMIT();
    };

    float acc[2][8][4];
#pragma unroll
    for (int mt = 0; mt < 2; mt++)
#pragma unroll
        for (int n8 = 0; n8 < 8; n8++)
#pragma unroll
            for (int q = 0; q < 4; q++) acc[mt][n8][q] = 0.f;

    // prologue: group 0
    cpB(0, 0);
    loadA(0);
    stsA(0);
    CP_WAIT0();
    __syncthreads();

    for (int g = 0; g < 8; g++) {
        int cur = g & 1, nxt = cur ^ 1;
        if (g < 7) { cpB(g + 1, nxt); loadA(g + 1); }
        uint32_t bufb = sb + cur * SM5_BUF;
        uint32_t ab = bufb + SM5_A;
        uint32_t bb = bufb + SM5_B;
#pragma unroll
        for (int ks = 0; ks < 4; ks++) {
            uint32_t af[2][4];
#pragma unroll
            for (int mt = 0; mt < 2; mt++) {
                int r = wm * 32 + mt * 16 + (lane & 7) + ((lane >> 3) & 1) * 8;
                int cB = ks * 32 + (lane >> 4) * 16;
                ldsm4(af[mt], ab + sw128(r * 128 + cB));
            }
            uint32_t bf[4][4];
#pragma unroll
            for (int nt = 0; nt < 4; nt++) {
                int rn = wn * 64 + nt * 16 + (lane & 7) + (lane >> 4) * 8;
                int cB = ks * 32 + ((lane >> 3) & 1) * 16;
                ldsm4(bf[nt], bb + sw128(rn * 128 + cB));
            }
#pragma unroll
            for (int mt = 0; mt < 2; mt++)
#pragma unroll
                for (int n8 = 0; n8 < 8; n8++)
                    mma16816(acc[mt][n8], af[mt], &bf[n8 >> 1][(n8 & 1) * 2]);
        }
        if (g < 7) {
            stsA(nxt);
            CP_WAIT0();
            __syncthreads();
        }
    }

    // ---- epilogue: +bias, relu, store ----
#pragma unroll
    for (int mt = 0; mt < 2; mt++) {
#pragma unroll
        for (int n8 = 0; n8 < 8; n8++) {
            int r = row0 + wm * 32 + mt * 16 + (lane >> 2);
            int col = wn * 64 + n8 * 8 + (lane & 3) * 2;
            float2 bv = *(const float2*)&bias[col];
            if (r < M) {
                float2 o;
                o.x = fmaxf(acc[mt][n8][0] + bv.x, 0.f);
                o.y = fmaxf(acc[mt][n8][1] + bv.y, 0.f);
                *(float2*)&g_h1[(size_t)r * HDIM + col] = o;
            }
            if (r + 8 < M) {
                float2 o;
                o.x = fmaxf(acc[mt][n8][2] + bv.x, 0.f);
                o.y = fmaxf(acc[mt][n8][3] + bv.y, 0.f);
                *(float2*)&g_h1[(size_t)(r + 8) * HDIM + col] = o;
            }
        }
    }
}

// ---------------- k6: layer-2 edge aggregation (compacted edges) ------------
__global__ void k6_agg2() {
    int n2 = g_e2count; if (n2 > E2MAX) n2 = E2MAX;
    int w = (blockIdx.x * blockDim.x + threadIdx.x) >> 5;
    int lane = threadIdx.x & 31;
    int nw = (gridDim.x * blockDim.x) >> 5;
    for (int i = w; i < n2; i += nw) {
        int s = g_e2src[i];
        int bin = g_e2bin[i];
        int sid = g_s1id[s];
        if (sid < 0) continue;  // safety
        float4 v = *(const float4*)&g_h1[(size_t)sid * HDIM + lane * 4];
        red_add_v4(&g_agg2[(size_t)bin * HDIM + lane * 4], v);
    }
}

// ---------------- k7: GEMM2: node = [agg2/c | h1_T] @ [Wrel2;Wroot2] + b2 ----
__global__ __launch_bounds__(256) void k7_gemm_node(
    const float* __restrict__ Wrel, const float* __restrict__ Wroot,
    const float* __restrict__ bias) {
    int M = g_tcount; if (M > TMAXC) M = TMAXC;
    int row0 = blockIdx.x * 64;
    if (row0 >= M) return;
    __shared__ __align__(16) float As[16][64];
    __shared__ __align__(16) float Bs[16][64];
    int tid = threadIdx.x;
    int rg = tid >> 4;
    int cg = tid & 15;
    float acc[4][4];
#pragma unroll
    for (int m = 0; m < 4; m++)
#pragma unroll
        for (int n = 0; n < 4; n++) acc[m][n] = 0.f;

    int a_i = tid >> 2;
    int a_kk = (tid & 3) * 4;
    int gi = row0 + a_i;
    int hsrc = (gi < M) ? g_t2s1[gi] : 0;

    for (int kt = 0; kt < 32; kt++) {
        int k0 = kt * 16;
        float4 av = make_float4(0.f, 0.f, 0.f, 0.f);
        if (gi < M) {
            int k = k0 + a_kk;
            int seg = k >> 7;
            if (seg < 3) {
                av = *(const float4*)&g_agg2[((size_t)(seg * TMAXC + gi)) * HDIM + (k & 127)];
                int c = g_cnt2[seg * TMAXC + gi];
                float inv = 1.0f / (float)(c > 1 ? c : 1);
                av.x *= inv; av.y *= inv; av.z *= inv; av.w *= inv;
            } else {
                av = *(const float4*)&g_h1[(size_t)hsrc * HDIM + (k - 384)];
            }
        }
        As[a_kk + 0][a_i] = av.x;
        As[a_kk + 1][a_i] = av.y;
        As[a_kk + 2][a_i] = av.z;
        As[a_kk + 3][a_i] = av.w;
        {
            int kk = tid >> 4, col = (tid & 15) * 4;
            int k = k0 + kk;
            const float* srcp = (k < 384) ? &Wrel[(size_t)k * EDIM + col]
                                          : &Wroot[(size_t)(k - 384) * EDIM + col];
            *(float4*)&Bs[kk][col] = *(const float4*)srcp;
        }
        __syncthreads();
#pragma unroll
        for (int kk = 0; kk < 16; kk++) {
            float4 ta = *(float4*)&As[kk][rg * 4];
            float a4[4] = {ta.x, ta.y, ta.z, ta.w};
            float4 bb = *(float4*)&Bs[kk][cg * 4];
            float b4[4] = {bb.x, bb.y, bb.z, bb.w};
#pragma unroll
            for (int m = 0; m < 4; m++)
#pragma unroll
                for (int n = 0; n < 4; n++) acc[m][n] += a4[m] * b4[n];
        }
        __syncthreads();
    }
    float4 bv = *(const float4*)&bias[cg * 4];
#pragma unroll
    for (int m = 0; m < 4; m++) {
        int row = row0 + rg * 4 + m;
        if (row < M) {
            float4 o;
            o.x = acc[m][0] + bv.x;
            o.y = acc[m][1] + bv.y;
            o.z = acc[m][2] + bv.z;
            o.w = acc[m][3] + bv.w;
            *(float4*)&g_node[(size_t)row * EDIM + cg * 4] = o;
        }
    }
}

// ---------------- k8: out = tanh([node[nest]|node[food]] @ fc_W + fc_b) ------
__global__ void k8_final(const int* __restrict__ nest, const int* __restrict__ food,
                         const float* __restrict__ fcW, const float* __restrict__ fcb,
                         float* __restrict__ out) {
    __shared__ float pr[128];
    int b = blockIdx.x;
    int h = threadIdx.x;    // 0..127
    if (h < 64) {
        int tn = g_tid[nest[b]];
        pr[h] = g_node[tn * EDIM + h];
    } else {
        int tf = g_tid[food[b]];
        pr[h] = g_node[tf * EDIM + (h - 64)];
    }
    __syncthreads();
    float acc = fcb[h];
#pragma unroll 8
    for (int k = 0; k < 128; k++) acc = fmaf(pr[k], fcW[k * HDIM + h], acc);
    out[(size_t)b * HDIM + h] = tanhf(acc);
}

// ---------------- launch ----------------
extern "C" void kernel_launch(void* const* d_in, const int* in_sizes, int n_in,
                              void* d_out, int out_size) {
    const float* x      = (const float*)d_in[0];
    const int*   esrc   = (const int*)d_in[1];
    const int*   edst   = (const int*)d_in[2];
    const int*   etyp   = (const int*)d_in[3];
    // d_in[4] = edge_attr (unused by the reference output)
    const int*   nest   = (const int*)d_in[5];
    const int*   food   = (const int*)d_in[6];
    const float* Wrel1  = (const float*)d_in[7];
    const float* Wroot1 = (const float*)d_in[8];
    const float* b1     = (const float*)d_in[9];
    const float* Wrel2  = (const float*)d_in[10];
    const float* Wroot2 = (const float*)d_in[11];
    const float* b2     = (const float*)d_in[12];
    const float* fcW    = (const float*)d_in[13];
    const float* fcb    = (const float*)d_in[14];
    float* out = (float*)d_out;

    int N = in_sizes[0] / FDIM;
    int E = in_sizes[1];
    int B = in_sizes[5];

    cudaFuncSetAttribute(k5_mma, cudaFuncAttributeMaxDynamicSharedMemorySize, SM5_TOTAL);

    int scanBlocks = (E + 255) / 256;

    k0_init<<<1024, 256>>>(N, Wrel1, Wroot1, x);
    k1_targets<<<(2 * B + 255) / 256, 256>>>(nest, food, B);
    k2_scan<<<scanBlocks + ZERO_BLOCKS, 256>>>(esrc, edst, etyp, E, scanBlocks);
    k4_agg1<<<4736, 256>>>(esrc, edst, etyp, E);
    k5_mma<<<S1MAX / 128, 256, SM5_TOTAL>>>(x, b1);
    k6_agg2<<<2048, 256>>>();
    k7_gemm_node<<<TMAXC / 64, 256>>>(Wrel2, Wroot2, b2);
    k8_final<<<B, 128>>>(nest, food, fcW, fcb, out);
}

// round 17
// speedup vs baseline: 1.1390x; 1.0052x over previous
#include <cuda_runtime.h>
#include <cuda_fp16.h>
#include <cstdint>

// ---------------- problem constants (fixed shapes) ----------------
#define NMAX   100000
#define FDIM   128
#define HDIM   128
#define EDIM   64
#define RREL   3
#define TMAXC  2048      // max unique targets (2*B)
#define S1MAX  49152     // max |S1| (expected ~30K)
#define E2MAX  131072    // max layer-2 edges (expected ~33K)
#define NBITW  4096      // bitmap words (NMAX/32 = 3125, padded)

#define ZERO_BLOCKS 2048

// ---------------- device scratch (static, no allocation) ----------------
__device__ int      g_tid[NMAX];       // node -> target compact id (-1 none)
__device__ int      g_s1id[NMAX];      // node -> S1 compact id (-1 none)
__device__ unsigned g_tbit[NBITW];     // T membership bitmap (12.5 KB, L1-resident)
__device__ unsigned g_s1bit[NBITW];    // S1 membership bitmap
__device__ int      g_tnodes[TMAXC];
__device__ int      g_t2s1[TMAXC];     // target idx -> s1 idx
__device__ int      g_s1nodes[S1MAX];
__device__ int      g_tcount;
__device__ int      g_s1count;
__device__ int      g_e2count;
__device__ int      g_e2src[E2MAX];
__device__ int      g_e2bin[E2MAX];
// agg1 packed by node: [sid][RREL][FDIM] -> live prefix is dense
__device__ float    g_agg1[(size_t)S1MAX * RREL * FDIM];   // ~75.5 MB
__device__ int      g_cnt1[S1MAX * RREL];
__device__ float    g_h1[(size_t)S1MAX * HDIM];            // ~25 MB
__device__ float    g_agg2[RREL * TMAXC * HDIM];
__device__ int      g_cnt2[RREL * TMAXC];
__device__ float    g_node[TMAXC * EDIM];
// transposed fp16 layer-1 weights: [N=128][K=512]
__device__ __align__(16) unsigned short g_Wt1[HDIM * 512];
// fp16 copy of x for the edge-aggregation pass: [NMAX][FDIM]
__device__ __align__(16) unsigned short g_xh[(size_t)NMAX * FDIM];

__device__ __forceinline__ void red_add_v4(float* p, float4 v) {
    asm volatile("red.global.add.v4.f32 [%0], {%1,%2,%3,%4};"
                 :: "l"(p), "f"(v.x), "f"(v.y), "f"(v.z), "f"(v.w) : "memory");
}

__device__ __forceinline__ uint32_t smem_u32(const void* p) {
    uint32_t a;
    asm("{ .reg .u64 t; cvta.to.shared.u64 t, %1; cvt.u32.u64 %0, t; }"
        : "=r"(a) : "l"(p));
    return a;
}
__device__ __forceinline__ uint32_t sw128(uint32_t off) {
    return off ^ ((off >> 3) & 0x70);
}
__device__ __forceinline__ void ldsm4(uint32_t r[4], uint32_t addr) {
    asm volatile("ldmatrix.sync.aligned.m8n8.x4.shared.b16 {%0,%1,%2,%3}, [%4];"
                 : "=r"(r[0]), "=r"(r[1]), "=r"(r[2]), "=r"(r[3]) : "r"(addr));
}
__device__ __forceinline__ void mma16816(float* c, const uint32_t* a, const uint32_t* b) {
    asm volatile(
        "mma.sync.aligned.m16n8k16.row.col.f32.f16.f16.f32 "
        "{%0,%1,%2,%3}, {%4,%5,%6,%7}, {%8,%9}, {%0,%1,%2,%3};"
        : "+f"(c[0]), "+f"(c[1]), "+f"(c[2]), "+f"(c[3])
        : "r"(a[0]), "r"(a[1]), "r"(a[2]), "r"(a[3]), "r"(b[0]), "r"(b[1]));
}
__device__ __forceinline__ void cp_async16(uint32_t smem_dst, const void* gsrc) {
    asm volatile("cp.async.ca.shared.global [%0], [%1], 16;"
                 :: "r"(smem_dst), "l"(gsrc) : "memory");
}
#define CP_COMMIT() asm volatile("cp.async.commit_group;" ::: "memory")
#define CP_WAIT0()  asm volatile("cp.async.wait_group 0;" ::: "memory")

// ---------------- k0: init maps/counters/bitmaps + weight transpose + x->fp16
__global__ void k0_init(int N, const float* __restrict__ Wrel,
                        const float* __restrict__ Wroot,
                        const float* __restrict__ x) {
    int i = blockIdx.x * blockDim.x + threadIdx.x;
    int stride = gridDim.x * blockDim.x;
    for (int j = i; j < N; j += stride) { g_tid[j] = -1; g_s1id[j] = -1; }
    for (int j = i; j < NBITW; j += stride) { g_tbit[j] = 0u; g_s1bit[j] = 0u; }
    for (int j = i; j < RREL * S1MAX; j += stride) g_cnt1[j] = 0;
    for (int j = i; j < RREL * TMAXC; j += stride) g_cnt2[j] = 0;
    for (int j = i; j < RREL * TMAXC * HDIM; j += stride) g_agg2[j] = 0.f;
    for (int j = i; j < HDIM * 512; j += stride) {
        int n = j >> 9;
        int k = j & 511;
        float v = (k < 384) ? Wrel[(size_t)k * HDIM + n]
                            : Wroot[(size_t)(k - 384) * HDIM + n];
        g_Wt1[j] = __half_as_ushort(__float2half_rn(v));
    }
    // x -> fp16 (half2 per iteration)
    int nh2 = N * (FDIM / 2);
    for (int j = i; j < nh2; j += stride) {
        float2 v = *(const float2*)&x[(size_t)j * 2];
        __half2 h = __floats2half2_rn(v.x, v.y);
        *(uint32_t*)&g_xh[(size_t)j * 2] = *(uint32_t*)&h;
    }
    if (i == 0) { g_tcount = 0; g_s1count = 0; g_e2count = 0; }
}

// ---------------- k1: mark target set T = nest ∪ food (+ bitmaps) -----------
__global__ void k1_targets(const int* __restrict__ nest,
                           const int* __restrict__ food, int B) {
    int i = blockIdx.x * blockDim.x + threadIdx.x;
    if (i >= 2 * B) return;
    int v = (i < B) ? nest[i] : food[i - B];
    if (atomicCAS(&g_tid[v], -1, -2) == -1) {
        int id = atomicAdd(&g_tcount, 1);       // <= 2*B <= TMAXC
        g_tnodes[id] = v;
        int sid = atomicAdd(&g_s1count, 1);
        g_s1nodes[sid] = v;
        g_s1id[v] = sid;
        g_t2s1[id] = sid;
        g_tid[v] = id;
        atomicOr(&g_tbit[v >> 5], 1u << (v & 31));
        atomicOr(&g_s1bit[v >> 5], 1u << (v & 31));
    }
}

// ---------------- k2: fused edge scan (bitmap filter) + agg1 zeroing ---------
__global__ void k2_scan(const int* __restrict__ esrc, const int* __restrict__ edst,
                        const int* __restrict__ etyp, int E, int scanBlocks) {
    if ((int)blockIdx.x >= scanBlocks) {
        // ---- zero role ----
        const size_t per4 = (size_t)RREL * S1MAX * (FDIM / 4);
        float4* base = (float4*)g_agg1;
        float4 z = make_float4(0.f, 0.f, 0.f, 0.f);
        size_t start = (size_t)(blockIdx.x - scanBlocks) * blockDim.x + threadIdx.x;
        size_t stride = (size_t)ZERO_BLOCKS * blockDim.x;
        for (size_t j = start; j < per4; j += stride) base[j] = z;
        return;
    }
    // ---- scan role: L1-resident bitmap pre-filter, then id gather ----
    int e = blockIdx.x * blockDim.x + threadIdx.x;
    bool pass = false;
    int d = -1;
    if (e < E) {
        d = edst[e];
        pass = (__ldg(&g_tbit[d >> 5]) >> (d & 31)) & 1u;
    }
    unsigned mask = __ballot_sync(0xffffffffu, pass);
    if (!pass) return;
    int td = g_tid[d];
    int t = etyp[e];
    int s = esrc[e];
    int lane = threadIdx.x & 31;
    int leader = __ffs(mask) - 1;
    int rank = __popc(mask & ((1u << lane) - 1));
    int base = 0;
    if (lane == leader) base = atomicAdd(&g_e2count, __popc(mask));
    base = __shfl_sync(mask, base, leader);
    int idx = base + rank;
    int bin = t * TMAXC + td;
    atomicAdd(&g_cnt2[bin], 1);
    if (idx < E2MAX) { g_e2src[idx] = s; g_e2bin[idx] = bin; }
    if (atomicCAS(&g_s1id[s], -1, -2) == -1) {
        int id = atomicAdd(&g_s1count, 1);
        if (id < S1MAX) {
            g_s1nodes[id] = s;
            g_s1id[s] = id;
            atomicOr(&g_s1bit[s >> 5], 1u << (s & 31));
        }
    }
}

// ---------------- k4: layer-1 aggregation, bitmap filter + packed bins -------
__global__ void k4_agg1(const int* __restrict__ esrc, const int* __restrict__ edst,
                        const int* __restrict__ etyp, int E) {
    int lane = threadIdx.x & 31;
    int warpId = (blockIdx.x * blockDim.x + threadIdx.x) >> 5;
    int nwarp = (gridDim.x * blockDim.x) >> 5;
    for (int e0 = warpId * 32; e0 < E; e0 += nwarp * 32) {
        int e = e0 + lane;
        bool pass = false;
        int s = 0, bin = 0;
        if (e < E) {
            int d = edst[e];
            if ((__ldg(&g_s1bit[d >> 5]) >> (d & 31)) & 1u) {
                int sid = g_s1id[d];
                pass = true;
                s = esrc[e];
                bin = sid * RREL + etyp[e];
            }
        }
        unsigned mask = __ballot_sync(0xffffffffu, pass);
        while (mask) {
            int src_lane = __ffs(mask) - 1;
            mask &= mask - 1;
            int ss = __shfl_sync(0xffffffffu, s, src_lane);
            int bb = __shfl_sync(0xffffffffu, bin, src_lane);
            if (lane == 0) atomicAdd(&g_cnt1[bb], 1);
            uint2 u = *(const uint2*)&g_xh[(size_t)ss * FDIM + lane * 4];
            __half2 h0 = *(__half2*)&u.x;
            __half2 h1 = *(__half2*)&u.y;
            float2 f0 = __half22float2(h0);
            float2 f1 = __half22float2(h1);
            float4 v = make_float4(f0.x, f0.y, f1.x, f1.y);
            red_add_v4(&g_agg1[(size_t)bb * FDIM + lane * 4], v);
        }
    }
}

// ---------------- k5: mma.sync fp16 GEMM1 (single pass) ----------------
// h1 = relu([agg1/c | x] @ [Wrel1;Wroot1] + b1)
// Per CTA: BM=128, N=128, K=512 in 8 groups of 64. Double-buffered (2 x 32KB)
#define SM5_BUF 32768
#define SM5_A   0
#define SM5_B   16384
#define SM5_TOTAL (2 * SM5_BUF)

__global__ __launch_bounds__(256) void k5_mma(const float* __restrict__ x,
                                              const float* __restrict__ bias) {
    extern __shared__ char smem[];
    int M = g_s1count; if (M > S1MAX) M = S1MAX;
    int row0 = blockIdx.x * 128;
    if (row0 >= M) return;
    uint32_t sb = smem_u32(smem);
    int tid = threadIdx.x;
    int wid = tid >> 5;
    int lane = tid & 31;
    int wm = wid >> 1;          // 0..3  (warp m tile: 32 rows)
    int wn = wid & 1;           // 0..1  (warp n tile: 64 cols)

    int row  = tid >> 1;        // 0..127 (loader row)
    int half = tid & 1;         // cols half*32..+32 of the 64-chunk
    int gi = row0 + row;
    bool valid = gi < M;
    int gR = valid ? gi : 0;
    int anode = valid ? g_s1nodes[gR] : 0;

    float4 va[8];
    // ---- group A load into regs (packed agg1 layout [sid][RREL][FDIM]) ----
    auto loadA = [&](int g) {
        const float* src;
        float inv = 1.0f;
        if (g < 6) {
            int seg = g >> 1;
            src = &g_agg1[((size_t)(gR * RREL + seg)) * FDIM + (g & 1) * 64 + half * 32];
            int c = g_cnt1[gR * RREL + seg];
            inv = 1.0f / (float)(c > 1 ? c : 1);
        } else {
            src = &x[(size_t)anode * FDIM + (g - 6) * 64 + half * 32];
        }
#pragma unroll
        for (int j = 0; j < 8; j++) {
            float4 v = make_float4(0.f, 0.f, 0.f, 0.f);
            if (valid) {
                v = *(const float4*)&src[j * 4];
                if (g < 6) { v.x *= inv; v.y *= inv; v.z *= inv; v.w *= inv; }
            }
            va[j] = v;
        }
    };
    // ---- convert + STS A (fp16) ----
    auto stsA = [&](int buf) {
#pragma unroll
        for (int j = 0; j < 8; j++) {
            float4 v = va[j];
            __half2 h01 = __floats2half2_rn(v.x, v.y);
            __half2 h23 = __floats2half2_rn(v.z, v.w);
            uint32_t off = sw128(row * 128 + (half * 32 + j * 4) * 2);
            uint2 ph;
            ph.x = *(uint32_t*)&h01; ph.y = *(uint32_t*)&h23;
            *(uint2*)(smem + buf * SM5_BUF + SM5_A + off) = ph;
        }
    };
    // ---- cp.async B tile (fp16) ----
    auto cpB = [&](int g, int buf) {
        uint32_t base = sb + buf * SM5_BUF;
        const unsigned short* sW = &g_Wt1[row * 512 + g * 64 + half * 32];
#pragma unroll
        for (int j = 0; j < 4; j++) {
            uint32_t off = sw128(row * 128 + (half * 32 + j * 8) * 2);
            cp_async16(base + SM5_B + off, sW + j * 8);
        }
        CP_COMMIT();
    };

    float acc[2][8][4];
#pragma unroll
    for (int mt = 0; mt < 2; mt++)
#pragma unroll
        for (int n8 = 0; n8 < 8; n8++)
#pragma unroll
            for (int q = 0; q < 4; q++) acc[mt][n8][q] = 0.f;

    // prologue: group 0
    cpB(0, 0);
    loadA(0);
    stsA(0);
    CP_WAIT0();
    __syncthreads();

    for (int g = 0; g < 8; g++) {
        int cur = g & 1, nxt = cur ^ 1;
        if (g < 7) { cpB(g + 1, nxt); loadA(g + 1); }
        uint32_t bufb = sb + cur * SM5_BUF;
        uint32_t ab = bufb + SM5_A;
        uint32_t bb = bufb + SM5_B;
#pragma unroll
        for (int ks = 0; ks < 4; ks++) {
            uint32_t af[2][4];
#pragma unroll
            for (int mt = 0; mt < 2; mt++) {
                int r = wm * 32 + mt * 16 + (lane & 7) + ((lane >> 3) & 1) * 8;
                int cB = ks * 32 + (lane >> 4) * 16;
                ldsm4(af[mt], ab + sw128(r * 128 + cB));
            }
            uint32_t bf[4][4];
#pragma unroll
            for (int nt = 0; nt < 4; nt++) {
                int rn = wn * 64 + nt * 16 + (lane & 7) + (lane >> 4) * 8;
                int cB = ks * 32 + ((lane >> 3) & 1) * 16;
                ldsm4(bf[nt], bb + sw128(rn * 128 + cB));
            }
#pragma unroll
            for (int mt = 0; mt < 2; mt++)
#pragma unroll
                for (int n8 = 0; n8 < 8; n8++)
                    mma16816(acc[mt][n8], af[mt], &bf[n8 >> 1][(n8 & 1) * 2]);
        }
        if (g < 7) {
            stsA(nxt);
            CP_WAIT0();
            __syncthreads();
        }
    }

    // ---- epilogue: +bias, relu, store ----
#pragma unroll
    for (int mt = 0; mt < 2; mt++) {
#pragma unroll
        for (int n8 = 0; n8 < 8; n8++) {
            int r = row0 + wm * 32 + mt * 16 + (lane >> 2);
            int col = wn * 64 + n8 * 8 + (lane & 3) * 2;
            float2 bv = *(const float2*)&bias[col];
            if (r < M) {
                float2 o;
                o.x = fmaxf(acc[mt][n8][0] + bv.x, 0.f);
                o.y = fmaxf(acc[mt][n8][1] + bv.y, 0.f);
                *(float2*)&g_h1[(size_t)r * HDIM + col] = o;
            }
            if (r + 8 < M) {
                float2 o;
                o.x = fmaxf(acc[mt][n8][2] + bv.x, 0.f);
                o.y = fmaxf(acc[mt][n8][3] + bv.y, 0.f);
                *(float2*)&g_h1[(size_t)(r + 8) * HDIM + col] = o;
            }
        }
    }
}

// ---------------- k6: layer-2 edge aggregation (compacted edges) ------------
__global__ void k6_agg2() {
    int n2 = g_e2count; if (n2 > E2MAX) n2 = E2MAX;
    int w = (blockIdx.x * blockDim.x + threadIdx.x) >> 5;
    int lane = threadIdx.x & 31;
    int nw = (gridDim.x * blockDim.x) >> 5;
    for (int i = w; i < n2; i += nw) {
        int s = g_e2src[i];
        int bin = g_e2bin[i];
        int sid = g_s1id[s];
        if (sid < 0) continue;  // safety
        float4 v = *(const float4*)&g_h1[(size_t)sid * HDIM + lane * 4];
        red_add_v4(&g_agg2[(size_t)bin * HDIM + lane * 4], v);
    }
}

// ---------------- k7: GEMM2: node = [agg2/c | h1_T] @ [Wrel2;Wroot2] + b2 ----
__global__ __launch_bounds__(256) void k7_gemm_node(
    const float* __restrict__ Wrel, const float* __restrict__ Wroot,
    const float* __restrict__ bias) {
    int M = g_tcount; if (M > TMAXC) M = TMAXC;
    int row0 = blockIdx.x * 64;
    if (row0 >= M) return;
    __shared__ __align__(16) float As[16][64];
    __shared__ __align__(16) float Bs[16][64];
    int tid = threadIdx.x;
    int rg = tid >> 4;
    int cg = tid & 15;
    float acc[4][4];
#pragma unroll
    for (int m = 0; m < 4; m++)
#pragma unroll
        for (int n = 0; n < 4; n++) acc[m][n] = 0.f;

    int a_i = tid >> 2;
    int a_kk = (tid & 3) * 4;
    int gi = row0 + a_i;
    int hsrc = (gi < M) ? g_t2s1[gi] : 0;

    for (int kt = 0; kt < 32; kt++) {
        int k0 = kt * 16;
        float4 av = make_float4(0.f, 0.f, 0.f, 0.f);
        if (gi < M) {
            int k = k0 + a_kk;
            int seg = k >> 7;
            if (seg < 3) {
                av = *(const float4*)&g_agg2[((size_t)(seg * TMAXC + gi)) * HDIM + (k & 127)];
                int c = g_cnt2[seg * TMAXC + gi];
                float inv = 1.0f / (float)(c > 1 ? c : 1);
                av.x *= inv; av.y *= inv; av.z *= inv; av.w *= inv;
            } else {
                av = *(const float4*)&g_h1[(size_t)hsrc * HDIM + (k - 384)];
            }
        }
        As[a_kk + 0][a_i] = av.x;
        As[a_kk + 1][a_i] = av.y;
        As[a_kk + 2][a_i] = av.z;
        As[a_kk + 3][a_i] = av.w;
        {
            int kk = tid >> 4, col = (tid & 15) * 4;
            int k = k0 + kk;
            const float* srcp = (k < 384) ? &Wrel[(size_t)k * EDIM + col]
                                          : &Wroot[(size_t)(k - 384) * EDIM + col];
            *(float4*)&Bs[kk][col] = *(const float4*)srcp;
        }
        __syncthreads();
#pragma unroll
        for (int kk = 0; kk < 16; kk++) {
            float4 ta = *(float4*)&As[kk][rg * 4];
            float a4[4] = {ta.x, ta.y, ta.z, ta.w};
            float4 bb = *(float4*)&Bs[kk][cg * 4];
            float b4[4] = {bb.x, bb.y, bb.z, bb.w};
#pragma unroll
            for (int m = 0; m < 4; m++)
#pragma unroll
                for (int n = 0; n < 4; n++) acc[m][n] += a4[m] * b4[n];
        }
        __syncthreads();
    }
    float4 bv = *(const float4*)&bias[cg * 4];
#pragma unroll
    for (int m = 0; m < 4; m++) {
        int row = row0 + rg * 4 + m;
        if (row < M) {
            float4 o;
            o.x = acc[m][0] + bv.x;
            o.y = acc[m][1] + bv.y;
            o.z = acc[m][2] + bv.z;
            o.w = acc[m][3] + bv.w;
            *(float4*)&g_node[(size_t)row * EDIM + cg * 4] = o;
        }
    }
}

// ---------------- k8: out = tanh([node[nest]|node[food]] @ fc_W + fc_b) ------
__global__ void k8_final(const int* __restrict__ nest, const int* __restrict__ food,
                         const float* __restrict__ fcW, const float* __restrict__ fcb,
                         float* __restrict__ out) {
    __shared__ float pr[128];
    int b = blockIdx.x;
    int h = threadIdx.x;    // 0..127
    if (h < 64) {
        int tn = g_tid[nest[b]];
        pr[h] = g_node[tn * EDIM + h];
    } else {
        int tf = g_tid[food[b]];
        pr[h] = g_node[tf * EDIM + (h - 64)];
    }
    __syncthreads();
    float acc = fcb[h];
#pragma unroll 8
    for (int k = 0; k < 128; k++) acc = fmaf(pr[k], fcW[k * HDIM + h], acc);
    out[(size_t)b * HDIM + h] = tanhf(acc);
}

// ---------------- launch ----------------
extern "C" void kernel_launch(void* const* d_in, const int* in_sizes, int n_in,
                              void* d_out, int out_size) {
    const float* x      = (const float*)d_in[0];
    const int*   esrc   = (const int*)d_in[1];
    const int*   edst   = (const int*)d_in[2];
    const int*   etyp   = (const int*)d_in[3];
    // d_in[4] = edge_attr (unused by the reference output)
    const int*   nest   = (const int*)d_in[5];
    const int*   food   = (const int*)d_in[6];
    const float* Wrel1  = (const float*)d_in[7];
    const float* Wroot1 = (const float*)d_in[8];
    const float* b1     = (const float*)d_in[9];
    const float* Wrel2  = (const float*)d_in[10];
    const float* Wroot2 = (const float*)d_in[11];
    const float* b2     = (const float*)d_in[12];
    const float* fcW    = (const float*)d_in[13];
    const float* fcb    = (const float*)d_in[14];
    float* out = (float*)d_out;

    int N = in_sizes[0] / FDIM;
    int E = in_sizes[1];
    int B = in_sizes[5];

    cudaFuncSetAttribute(k5_mma, cudaFuncAttributeMaxDynamicSharedMemorySize, SM5_TOTAL);

    int scanBlocks = (E + 255) / 256;

    k0_init<<<1024, 256>>>(N, Wrel1, Wroot1, x);
    k1_targets<<<(2 * B + 255) / 256, 256>>>(nest, food, B);
    k2_scan<<<scanBlocks + ZERO_BLOCKS, 256>>>(esrc, edst, etyp, E, scanBlocks);
    k4_agg1<<<4736, 256>>>(esrc, edst, etyp, E);
    k5_mma<<<S1MAX / 128, 256, SM5_TOTAL>>>(x, b1);
    k6_agg2<<<2048, 256>>>();
    k7_gemm_node<<<TMAXC / 64, 256>>>(Wrel2, Wroot2, b2);
    k8_final<<<B, 128>>>(nest, food, fcW, fcb, out);
}